// round 14
// baseline (speedup 1.0000x reference)
#include <cuda_runtime.h>
#include <cuda_bf16.h>
#include <math.h>
#include <stdint.h>

#define D_MODEL 2048
#define N_HEAD  16
#define HEAD_DIM 128
#define BATCH   2
#define SEQ     2048

// ---------------------------------------------------------------------------
// Static scratch (no cudaMalloc anywhere)
// ---------------------------------------------------------------------------
static __device__ float g_rope[(size_t)SEQ * 128];                // cos/sin table
static __device__ __nv_bfloat16 g_Ahi[(size_t)BATCH * SEQ * D_MODEL];
static __device__ __nv_bfloat16 g_Alo[(size_t)BATCH * SEQ * D_MODEL];
static __device__ __nv_bfloat16 g_Wqkv_hi[(size_t)3 * D_MODEL * D_MODEL]; // [N][K]
static __device__ __nv_bfloat16 g_Wqkv_lo[(size_t)3 * D_MODEL * D_MODEL];
static __device__ __nv_bfloat16 g_Wproj_hi[(size_t)D_MODEL * D_MODEL];
static __device__ __nv_bfloat16 g_Wproj_lo[(size_t)D_MODEL * D_MODEL];
// head-major prepped attention operands: [b][h][t][d]
static __device__ __nv_bfloat16 g_Qhi[(size_t)BATCH * SEQ * D_MODEL];
static __device__ __nv_bfloat16 g_Qlo[(size_t)BATCH * SEQ * D_MODEL];
static __device__ __nv_bfloat16 g_Khi[(size_t)BATCH * SEQ * D_MODEL];
static __device__ __nv_bfloat16 g_Klo[(size_t)BATCH * SEQ * D_MODEL];
static __device__ __nv_bfloat16 g_Vhi[(size_t)BATCH * SEQ * D_MODEL];
static __device__ __nv_bfloat16 g_Vlo[(size_t)BATCH * SEQ * D_MODEL];

// ---------------------------------------------------------------------------
// PTX helpers (sm_80+ subset: cp.async / ldmatrix / mma.sync)
// ---------------------------------------------------------------------------
__device__ __forceinline__ uint32_t smem_to_u32(const void* smem_ptr) {
    uint32_t addr;
    asm("{ .reg .u64 tmp; cvta.to.shared.u64 tmp, %1; cvt.u32.u64 %0, tmp; }"
        : "=r"(addr) : "l"(smem_ptr));
    return addr;
}

__device__ __forceinline__ void cp_async16(uint32_t smem_dst, const void* gmem_src) {
    asm volatile("cp.async.cg.shared.global.L2::128B [%0], [%1], 16;"
                 :: "r"(smem_dst), "l"(__cvta_generic_to_global(gmem_src)));
}
#define CP_ASYNC_COMMIT() asm volatile("cp.async.commit_group;" ::: "memory")
#define CP_ASYNC_WAIT_1() asm volatile("cp.async.wait_group 1;" ::: "memory")

__device__ __forceinline__ void ldsm4(uint32_t* r, uint32_t addr) {
    asm volatile("ldmatrix.sync.aligned.m8n8.x4.shared.b16 {%0,%1,%2,%3}, [%4];"
                 : "=r"(r[0]), "=r"(r[1]), "=r"(r[2]), "=r"(r[3]) : "r"(addr));
}
__device__ __forceinline__ void ldsm4t(uint32_t* r, uint32_t addr) {
    asm volatile("ldmatrix.sync.aligned.m8n8.x4.trans.shared.b16 {%0,%1,%2,%3}, [%4];"
                 : "=r"(r[0]), "=r"(r[1]), "=r"(r[2]), "=r"(r[3]) : "r"(addr));
}

__device__ __forceinline__ void mma_bf16(float* c, const uint32_t* a,
                                         uint32_t b0, uint32_t b1) {
    asm volatile(
        "mma.sync.aligned.m16n8k16.row.col.f32.bf16.bf16.f32 "
        "{%0,%1,%2,%3}, {%4,%5,%6,%7}, {%8,%9}, {%0,%1,%2,%3};"
        : "+f"(c[0]), "+f"(c[1]), "+f"(c[2]), "+f"(c[3])
        : "r"(a[0]), "r"(a[1]), "r"(a[2]), "r"(a[3]), "r"(b0), "r"(b1));
}

// pack (s0 -> low bf16, s1 -> high bf16) into hi; residuals into lo.
__device__ __forceinline__ void split2(float s0, float s1, uint32_t& hi, uint32_t& lo) {
    asm("cvt.rn.bf16x2.f32 %0, %1, %2;" : "=r"(hi) : "f"(s1), "f"(s0));
    __nv_bfloat162 hv = *reinterpret_cast<__nv_bfloat162*>(&hi);
    float r0 = s0 - __bfloat162float(hv.x);
    float r1 = s1 - __bfloat162float(hv.y);
    asm("cvt.rn.bf16x2.f32 %0, %1, %2;" : "=r"(lo) : "f"(r1), "f"(r0));
}

// ---------------------------------------------------------------------------
// RoPE table
// ---------------------------------------------------------------------------
__global__ void rope_table_kernel()
{
    const float RATE_C = 0.14391156831212787f; // ln(10000)/64
    int i = blockIdx.x * blockDim.x + threadIdx.x;  // t*64 + j
    int t = i >> 6, j = i & 63;
    float rate = expf(-RATE_C * (float)j);
    float sv, cv;
    sincosf((float)t * rate, &sv, &cv);
    g_rope[t * 128 + j]      = cv;
    g_rope[t * 128 + 64 + j] = sv;
}

// ---------------------------------------------------------------------------
// Elementwise split: fp32 -> (hi, lo) bf16 pair.
// ---------------------------------------------------------------------------
__global__ void split_kernel(const float* __restrict__ X,
                             __nv_bfloat16* __restrict__ hi,
                             __nv_bfloat16* __restrict__ lo, int n4)
{
    int i = blockIdx.x * blockDim.x + threadIdx.x;
    if (i >= n4) return;
    float4 v = *(const float4*)(X + (size_t)i * 4);
    __nv_bfloat16 h[4], l[4];
    float vv[4] = {v.x, v.y, v.z, v.w};
#pragma unroll
    for (int j = 0; j < 4; ++j) {
        h[j] = __float2bfloat16(vv[j]);
        l[j] = __float2bfloat16(vv[j] - __bfloat162float(h[j]));
    }
    *(uint2*)(hi + (size_t)i * 4) = *(uint2*)h;
    *(uint2*)(lo + (size_t)i * 4) = *(uint2*)l;
}

// ---------------------------------------------------------------------------
// Transpose + split: W[K,N] fp32 -> Thi/Tlo [N,K] bf16 (K-major for MMA B).
// ---------------------------------------------------------------------------
__global__ __launch_bounds__(256) void transpose_split_kernel(
    const float* __restrict__ W,
    __nv_bfloat16* __restrict__ Thi, __nv_bfloat16* __restrict__ Tlo,
    int K, int N)
{
    __shared__ float tile[64][65];
    const int k0 = blockIdx.y * 64;
    const int n0 = blockIdx.x * 64;
    const int tid = threadIdx.x;

#pragma unroll
    for (int j = 0; j < 4; ++j) {
        int idx = tid + j * 256;
        int r  = idx >> 4;
        int c4 = (idx & 15) * 4;
        float4 v = *(const float4*)(W + (size_t)(k0 + r) * N + n0 + c4);
        tile[r][c4 + 0] = v.x; tile[r][c4 + 1] = v.y;
        tile[r][c4 + 2] = v.z; tile[r][c4 + 3] = v.w;
    }
    __syncthreads();

    const int n  = tid >> 2;
    const int ks = (tid & 3) * 16;
    __nv_bfloat16 h[16], l[16];
#pragma unroll
    for (int j = 0; j < 16; ++j) {
        float v = tile[ks + j][n];
        h[j] = __float2bfloat16(v);
        l[j] = __float2bfloat16(v - __bfloat162float(h[j]));
    }
    size_t base = (size_t)(n0 + n) * K + k0 + ks;
    *(uint4*)(Thi + base)     = ((uint4*)h)[0];
    *(uint4*)(Thi + base + 8) = ((uint4*)h)[1];
    *(uint4*)(Tlo + base)     = ((uint4*)l)[0];
    *(uint4*)(Tlo + base + 8) = ((uint4*)l)[1];
}

// ---------------------------------------------------------------------------
// bf16x3 HMMA GEMM (unchanged from R9): 4 warps 2x2, 64x64 warp tiles,
// 3-stage XOR-swizzled cp.async pipeline, 1 barrier/iter, 2 CTAs/SM.
// ---------------------------------------------------------------------------
#define GB_OP     (128 * 64)                // 8192 B per operand tile
#define GB_STAGE  (4 * GB_OP)               // 32768 B
#define GB_NSTAGE 3
#define GB_SMEM   (GB_NSTAGE * GB_STAGE)    // 98304 B (>= 128*132*4 = 67584)

#define GB_SWIZ(row, c) ((uint32_t)((row) * 64 + (((c) ^ (((row) >> 1) & 3)) * 16)))

__device__ __forceinline__ void gemm_load_stage(
    uint32_t st,
    const __nv_bfloat16* __restrict__ Ahi, const __nv_bfloat16* __restrict__ Alo,
    const __nv_bfloat16* __restrict__ Bhi, const __nv_bfloat16* __restrict__ Blo,
    int bm, int bn, int k0, int K, int tid)
{
#pragma unroll
    for (int j = 0; j < 4; ++j) {
        int idx = tid + j * 128;            // 0..511
        int row = idx >> 2;                 // 0..127
        int c   = idx & 3;                  // 16B chunk within 64B row
        uint32_t off = GB_SWIZ(row, c);
        size_t ga = (size_t)(bm + row) * K + k0 + c * 8;
        size_t gb = (size_t)(bn + row) * K + k0 + c * 8;
        cp_async16(st + off,              Ahi + ga);
        cp_async16(st + GB_OP + off,      Alo + ga);
        cp_async16(st + 2 * GB_OP + off,  Bhi + gb);
        cp_async16(st + 3 * GB_OP + off,  Blo + gb);
    }
}

__global__ __launch_bounds__(128, 2) void gemm_bf16x3_kernel(
    const __nv_bfloat16* __restrict__ Ahi, const __nv_bfloat16* __restrict__ Alo,
    const __nv_bfloat16* __restrict__ Bhi, const __nv_bfloat16* __restrict__ Blo,
    const float* __restrict__ bias, float* __restrict__ C,
    int M, int N, int K, int fuse_qkv)
{
    extern __shared__ __align__(128) char smem[];
    const uint32_t sbase = smem_to_u32(smem);
    const int tid  = threadIdx.x;
    const int lane = tid & 31;
    const int wid  = tid >> 5;              // 0..3
    const int wm   = wid >> 1;              // 0..1 (64-row stripes)
    const int wn   = wid & 1;               // 0..1 (64-col stripes)
    const int bm   = blockIdx.y * 128;
    const int bn   = blockIdx.x * 128;

    float acc[4][8][4];
#pragma unroll
    for (int mi = 0; mi < 4; ++mi)
#pragma unroll
        for (int ni = 0; ni < 8; ++ni)
#pragma unroll
            for (int r = 0; r < 4; ++r) acc[mi][ni][r] = 0.f;

    const int nk = K / 32;

    gemm_load_stage(sbase,            Ahi, Alo, Bhi, Blo, bm, bn, 0,  K, tid);
    CP_ASYNC_COMMIT();
    gemm_load_stage(sbase + GB_STAGE, Ahi, Alo, Bhi, Blo, bm, bn, 32, K, tid);
    CP_ASYNC_COMMIT();

    const int lrowA = lane & 15, lcolA = lane >> 4;
    const int bg    = lane >> 3, blr  = lane & 7;

    for (int i = 0; i < nk; ++i) {
        const uint32_t st = sbase + (uint32_t)(i % GB_NSTAGE) * GB_STAGE;
        CP_ASYNC_WAIT_1();
        __syncthreads();

        if (i + 2 < nk) {
            gemm_load_stage(sbase + (uint32_t)((i + 2) % GB_NSTAGE) * GB_STAGE,
                            Ahi, Alo, Bhi, Blo, bm, bn, (i + 2) * 32, K, tid);
        }
        CP_ASYNC_COMMIT();

        const uint32_t aHi = st;
        const uint32_t aLo = st + GB_OP;
        const uint32_t bHi = st + 2 * GB_OP;
        const uint32_t bLo = st + 3 * GB_OP;

#pragma unroll
        for (int ks = 0; ks < 2; ++ks) {
            uint32_t ah[4][4], al[4][4];
#pragma unroll
            for (int mi = 0; mi < 4; ++mi) {
                int row = wm * 64 + mi * 16 + lrowA;
                uint32_t off = GB_SWIZ(row, ks * 2 + lcolA);
                ldsm4(ah[mi], aHi + off);
                ldsm4(al[mi], aLo + off);
            }
#pragma unroll
            for (int np = 0; np < 4; ++np) {
                uint32_t bh[4], bl[4];
                int row = wn * 64 + np * 16 + (bg >> 1) * 8 + blr;
                uint32_t off = GB_SWIZ(row, ks * 2 + (bg & 1));
                ldsm4(bh, bHi + off);
                ldsm4(bl, bLo + off);
#pragma unroll
                for (int mi = 0; mi < 4; ++mi)
#pragma unroll
                    for (int q = 0; q < 2; ++q) {
                        int ni = np * 2 + q, pr = q * 2;
                        mma_bf16(acc[mi][ni], ah[mi], bh[pr], bh[pr + 1]);
                        mma_bf16(acc[mi][ni], ah[mi], bl[pr], bl[pr + 1]);
                        mma_bf16(acc[mi][ni], al[mi], bh[pr], bh[pr + 1]);
                    }
            }
        }
    }

    const int gid = lane >> 2, tig = lane & 3;

    if (fuse_qkv == 0) {
#pragma unroll
        for (int mi = 0; mi < 4; ++mi)
#pragma unroll
            for (int ni = 0; ni < 8; ++ni) {
                int row = bm + wm * 64 + mi * 16 + gid;
                int col = bn + wn * 64 + ni * 8 + tig * 2;
                float2 bv = *(const float2*)(bias + col);
                float2 v0 = make_float2(acc[mi][ni][0] + bv.x, acc[mi][ni][1] + bv.y);
                float2 v1 = make_float2(acc[mi][ni][2] + bv.x, acc[mi][ni][3] + bv.y);
                *(float2*)(C + (size_t)row * N + col)       = v0;
                *(float2*)(C + (size_t)(row + 8) * N + col) = v1;
            }
        return;
    }

    // ---- fused QKV epilogue: rope/scale/split, head-major bf16 hi/lo ----
    __syncthreads();
    float* Cs = (float*)smem;                 // 128 x 132 fp32, reuses stages
#pragma unroll
    for (int mi = 0; mi < 4; ++mi)
#pragma unroll
        for (int ni = 0; ni < 8; ++ni) {
            int row = wm * 64 + mi * 16 + gid;
            int col = wn * 64 + ni * 8 + tig * 2;
            float2 bv = *(const float2*)(bias + bn + col);
            Cs[row * 132 + col]           = acc[mi][ni][0] + bv.x;
            Cs[row * 132 + col + 1]       = acc[mi][ni][1] + bv.y;
            Cs[(row + 8) * 132 + col]     = acc[mi][ni][2] + bv.x;
            Cs[(row + 8) * 132 + col + 1] = acc[mi][ni][3] + bv.y;
        }
    __syncthreads();

    const int sel = bn >> 11;                 // 0=Q, 1=K, 2=V
    const int hh  = (bn & 2047) >> 7;         // head
    __nv_bfloat16 *dh, *dl;
    if (sel == 0)      { dh = g_Qhi; dl = g_Qlo; }
    else if (sel == 1) { dh = g_Khi; dl = g_Klo; }
    else               { dh = g_Vhi; dl = g_Vlo; }
    const float SCALE = 0.08838834764831845f; // 1/sqrt(128)

    for (int i = tid; i < 128 * 32; i += 128) {
        int row = i >> 5, jp = (i & 31) * 2;
        int tg = bm + row, t = tg & (SEQ - 1), bb = tg >> 11;
        float x1a = Cs[row * 132 + jp],      x1b = Cs[row * 132 + jp + 1];
        float x2a = Cs[row * 132 + jp + 64], x2b = Cs[row * 132 + jp + 65];
        float y1a, y1b, y2a, y2b;
        if (sel < 2) {
            float cva = g_rope[t * 128 + jp],     sva = g_rope[t * 128 + 64 + jp];
            float cvb = g_rope[t * 128 + jp + 1], svb = g_rope[t * 128 + 64 + jp + 1];
            y1a = x1a * cva - x2a * sva;  y2a = x1a * sva + x2a * cva;
            y1b = x1b * cvb - x2b * svb;  y2b = x1b * svb + x2b * cvb;
            if (sel == 0) { y1a *= SCALE; y2a *= SCALE; y1b *= SCALE; y2b *= SCALE; }
        } else {
            y1a = x1a; y1b = x1b; y2a = x2a; y2b = x2b;
        }
        size_t base = ((size_t)(bb * N_HEAD + hh) * SEQ + t) * HEAD_DIM;
        uint32_t hi, lo;
        split2(y1a, y1b, hi, lo);
        *(uint32_t*)(dh + base + jp)      = hi;
        *(uint32_t*)(dl + base + jp)      = lo;
        split2(y2a, y2b, hi, lo);
        *(uint32_t*)(dh + base + jp + 64) = hi;
        *(uint32_t*)(dl + base + jp + 64) = lo;
    }
}

// ---------------------------------------------------------------------------
// MMA flash attention, R14: 128 threads = 4 warps x 32 q-rows (2 m-frags).
// Each K/V fragment feeds 2x the MMAs -> smem read traffic -39% per tile.
// Q in smem (re-read per tile), double-buffered KV, R9-proven sync schedule.
// ---------------------------------------------------------------------------
#define FA_TQ 128
#define FA_TK 64
#define FA_ROWB 272
#define FA_BUF  69632                 // KV buffer: KHI +0, KLO +17408, VHI +34816, VLO +52224
#define FA_SMEM (3 * FA_BUF)          // 208896: 2 KV buffers + Q area (hi/lo)

__device__ __forceinline__ void fa_load_kv(uint32_t buf, size_t bh_elem, int k0, int tid)
{
    size_t gbase = bh_elem + (size_t)k0 * HEAD_DIM;
    for (int i = tid; i < FA_TK * 16; i += 128) {
        int row = i >> 4, c = i & 15;
        uint32_t soff = (uint32_t)(row * FA_ROWB + c * 16);
        size_t   goff = gbase + (size_t)row * HEAD_DIM + c * 8;
        cp_async16(buf + soff,         g_Khi + goff);
        cp_async16(buf + 17408 + soff, g_Klo + goff);
        cp_async16(buf + 34816 + soff, g_Vhi + goff);
        cp_async16(buf + 52224 + soff, g_Vlo + goff);
    }
}

__global__ __launch_bounds__(128, 1) void flash_attn_mma_kernel()
{
    extern __shared__ __align__(128) char sm[];
    const uint32_t sbase = smem_to_u32(sm);

    const int tid  = threadIdx.x;
    const int lane = tid & 31;
    const int wid  = tid >> 5;                       // 0..3
    const int qt   = (gridDim.x - 1) - blockIdx.x;   // heavy tiles first
    const int q0   = qt * FA_TQ;
    const int b    = blockIdx.y >> 4;
    const int h    = blockIdx.y & 15;

    const size_t bh_elem = (size_t)(b * N_HEAD + h) * SEQ * HEAD_DIM;
    const int ktmax = 2 * qt + 1;                    // >= 1 always
    const uint32_t qarea = sbase + 2 * FA_BUF;       // QHI +0, QLO +34816

    // ---- prologue loads: Q + KV0 (group 0), KV1 (group 1) ----
    {
        size_t qbase = bh_elem + (size_t)q0 * HEAD_DIM;
        for (int i = tid; i < FA_TQ * 16; i += 128) {
            int row = i >> 4, c = i & 15;
            uint32_t soff = (uint32_t)(row * FA_ROWB + c * 16);
            size_t   goff = qbase + (size_t)row * HEAD_DIM + c * 8;
            cp_async16(qarea + soff,         g_Qhi + goff);
            cp_async16(qarea + 34816 + soff, g_Qlo + goff);
        }
    }
    fa_load_kv(sbase, bh_elem, 0, tid);
    CP_ASYNC_COMMIT();                               // g0: Q + KV0
    fa_load_kv(sbase + FA_BUF, bh_elem, FA_TK, tid);
    CP_ASYNC_COMMIT();                               // g1: KV1

    const int gid = lane >> 2, tig = lane & 3;
    const int lrowA = lane & 15, lcolA = lane >> 4;
    const int bg = lane >> 3, blr = lane & 7;
    const int wrow_lo = q0 + wid * 32;               // warp owns rows [wrow_lo, +31]

    float oacc[2][16][4];
#pragma unroll
    for (int mi = 0; mi < 2; ++mi)
#pragma unroll
        for (int ni = 0; ni < 16; ++ni)
#pragma unroll
            for (int r = 0; r < 4; ++r) oacc[mi][ni][r] = 0.f;
    float mrun[2][2], lrun[2][2];
#pragma unroll
    for (int mi = 0; mi < 2; ++mi) {
        mrun[mi][0] = -1e30f; mrun[mi][1] = -1e30f;
        lrun[mi][0] = 0.f;    lrun[mi][1] = 0.f;
    }

    for (int kt = 0; kt <= ktmax; ++kt) {
        const int k0 = kt * FA_TK;
        const uint32_t buf = sbase + (uint32_t)(kt & 1) * FA_BUF;
        CP_ASYNC_WAIT_1();          // KV[kt] (and Q) resident; KV[kt+1] may pend
        __syncthreads();

        if (k0 <= wrow_lo + 31) {   // warp-level causal skip
            // ---- S = Q @ K^T (32 rows x 64 cols), bf16x3 ----
            float sacc[2][8][4];
#pragma unroll
            for (int mi = 0; mi < 2; ++mi)
#pragma unroll
                for (int ni = 0; ni < 8; ++ni)
#pragma unroll
                    for (int r = 0; r < 4; ++r) sacc[mi][ni][r] = 0.f;

#pragma unroll
            for (int ks = 0; ks < 8; ++ks) {
                uint32_t qh0[4], ql0[4], qh1[4], ql1[4];
                uint32_t qoff0 = (uint32_t)((wid * 32 + lrowA) * FA_ROWB
                                            + (ks * 16 + lcolA * 8) * 2);
                uint32_t qoff1 = qoff0 + 16 * FA_ROWB;
                ldsm4(qh0, qarea + qoff0);
                ldsm4(ql0, qarea + 34816 + qoff0);
                ldsm4(qh1, qarea + qoff1);
                ldsm4(ql1, qarea + 34816 + qoff1);
#pragma unroll
                for (int np = 0; np < 4; ++np) {
                    uint32_t kh[4], kl[4];
                    uint32_t koff = (uint32_t)((np * 16 + (bg >> 1) * 8 + blr) * FA_ROWB
                                               + (ks * 16 + (bg & 1) * 8) * 2);
                    ldsm4(kh, buf + koff);
                    ldsm4(kl, buf + 17408 + koff);
#pragma unroll
                    for (int q = 0; q < 2; ++q) {
                        int ni = np * 2 + q, pr = q * 2;
                        mma_bf16(sacc[0][ni], qh0, kh[pr], kh[pr + 1]);
                        mma_bf16(sacc[0][ni], qh0, kl[pr], kl[pr + 1]);
                        mma_bf16(sacc[0][ni], ql0, kh[pr], kh[pr + 1]);
                        mma_bf16(sacc[1][ni], qh1, kh[pr], kh[pr + 1]);
                        mma_bf16(sacc[1][ni], qh1, kl[pr], kl[pr + 1]);
                        mma_bf16(sacc[1][ni], ql1, kh[pr], kh[pr + 1]);
                    }
                }
            }

            // ---- causal mask (partial tiles only) ----
            if (k0 + FA_TK - 1 > q0) {
#pragma unroll
                for (int mi = 0; mi < 2; ++mi) {
                    int row0 = wrow_lo + mi * 16 + gid, row1 = row0 + 8;
#pragma unroll
                    for (int ni = 0; ni < 8; ++ni) {
                        int col = k0 + ni * 8 + tig * 2;
                        if (col     > row0) sacc[mi][ni][0] = -1e30f;
                        if (col + 1 > row0) sacc[mi][ni][1] = -1e30f;
                        if (col     > row1) sacc[mi][ni][2] = -1e30f;
                        if (col + 1 > row1) sacc[mi][ni][3] = -1e30f;
                    }
                }
            }

            // ---- online softmax (per m-frag) ----
#pragma unroll
            for (int mi = 0; mi < 2; ++mi) {
                float mx0 = -1e30f, mx1 = -1e30f;
#pragma unroll
                for (int ni = 0; ni < 8; ++ni) {
                    mx0 = fmaxf(mx0, fmaxf(sacc[mi][ni][0], sacc[mi][ni][1]));
                    mx1 = fmaxf(mx1, fmaxf(sacc[mi][ni][2], sacc[mi][ni][3]));
                }
#pragma unroll
                for (int off = 1; off < 4; off <<= 1) {
                    mx0 = fmaxf(mx0, __shfl_xor_sync(0xffffffffu, mx0, off));
                    mx1 = fmaxf(mx1, __shfl_xor_sync(0xffffffffu, mx1, off));
                }
                float mn0 = fmaxf(mrun[mi][0], mx0), mn1 = fmaxf(mrun[mi][1], mx1);
                float a0 = __expf(mrun[mi][0] - mn0), a1 = __expf(mrun[mi][1] - mn1);
                mrun[mi][0] = mn0; mrun[mi][1] = mn1;
                float sum0 = 0.f, sum1 = 0.f;
#pragma unroll
                for (int ni = 0; ni < 8; ++ni) {
                    sacc[mi][ni][0] = __expf(sacc[mi][ni][0] - mn0);
                    sacc[mi][ni][1] = __expf(sacc[mi][ni][1] - mn0);
                    sacc[mi][ni][2] = __expf(sacc[mi][ni][2] - mn1);
                    sacc[mi][ni][3] = __expf(sacc[mi][ni][3] - mn1);
                    sum0 += sacc[mi][ni][0] + sacc[mi][ni][1];
                    sum1 += sacc[mi][ni][2] + sacc[mi][ni][3];
                }
#pragma unroll
                for (int off = 1; off < 4; off <<= 1) {
                    sum0 += __shfl_xor_sync(0xffffffffu, sum0, off);
                    sum1 += __shfl_xor_sync(0xffffffffu, sum1, off);
                }
                lrun[mi][0] = lrun[mi][0] * a0 + sum0;
                lrun[mi][1] = lrun[mi][1] * a1 + sum1;
#pragma unroll
                for (int ni = 0; ni < 16; ++ni) {
                    oacc[mi][ni][0] *= a0; oacc[mi][ni][1] *= a0;
                    oacc[mi][ni][2] *= a1; oacc[mi][ni][3] *= a1;
                }
            }

            // ---- O += P @ V, bf16x3 (V via trans ldmatrix, shared by m-frags) ----
            const uint32_t vhi = buf + 34816, vlo = buf + 52224;
#pragma unroll
            for (int kc = 0; kc < 4; ++kc) {
                uint32_t ah[2][4], al[2][4];
#pragma unroll
                for (int mi = 0; mi < 2; ++mi) {
                    split2(sacc[mi][2 * kc][0],     sacc[mi][2 * kc][1],     ah[mi][0], al[mi][0]);
                    split2(sacc[mi][2 * kc][2],     sacc[mi][2 * kc][3],     ah[mi][1], al[mi][1]);
                    split2(sacc[mi][2 * kc + 1][0], sacc[mi][2 * kc + 1][1], ah[mi][2], al[mi][2]);
                    split2(sacc[mi][2 * kc + 1][2], sacc[mi][2 * kc + 1][3], ah[mi][3], al[mi][3]);
                }
#pragma unroll
                for (int np = 0; np < 8; ++np) {
                    uint32_t vh[4], vl[4];
                    uint32_t voff = (uint32_t)((kc * 16 + (lane & 15)) * FA_ROWB
                                               + (np * 16 + (lane >> 4) * 8) * 2);
                    ldsm4t(vh, vhi + voff);
                    ldsm4t(vl, vlo + voff);
#pragma unroll
                    for (int q = 0; q < 2; ++q) {
                        int ni = np * 2 + q, pr = q * 2;
                        mma_bf16(oacc[0][ni], ah[0], vh[pr], vh[pr + 1]);
                        mma_bf16(oacc[0][ni], ah[0], vl[pr], vl[pr + 1]);
                        mma_bf16(oacc[0][ni], al[0], vh[pr], vh[pr + 1]);
                        mma_bf16(oacc[1][ni], ah[1], vh[pr], vh[pr + 1]);
                        mma_bf16(oacc[1][ni], ah[1], vl[pr], vl[pr + 1]);
                        mma_bf16(oacc[1][ni], al[1], vh[pr], vh[pr + 1]);
                    }
                }
            }
        }

        __syncthreads();            // all warps done reading buf before overwrite
        if (kt + 2 <= ktmax)
            fa_load_kv(sbase + (uint32_t)(kt & 1) * FA_BUF,
                       bh_elem, (kt + 2) * FA_TK, tid);
        CP_ASYNC_COMMIT();
    }

    // ---- epilogue: normalize, split to bf16 hi/lo, store ----
#pragma unroll
    for (int mi = 0; mi < 2; ++mi) {
        float inv0 = 1.f / lrun[mi][0], inv1 = 1.f / lrun[mi][1];
        int t0 = wrow_lo + mi * 16 + gid;
        size_t base0 = (size_t)(b * SEQ + t0) * D_MODEL + h * HEAD_DIM;
        size_t base1 = (size_t)(b * SEQ + t0 + 8) * D_MODEL + h * HEAD_DIM;
#pragma unroll
        for (int ni = 0; ni < 16; ++ni) {
            int col = ni * 8 + tig * 2;
            uint32_t hi, lo;
            split2(oacc[mi][ni][0] * inv0, oacc[mi][ni][1] * inv0, hi, lo);
            *(uint32_t*)(g_Ahi + base0 + col) = hi;
            *(uint32_t*)(g_Alo + base0 + col) = lo;
            split2(oacc[mi][ni][2] * inv1, oacc[mi][ni][3] * inv1, hi, lo);
            *(uint32_t*)(g_Ahi + base1 + col) = hi;
            *(uint32_t*)(g_Alo + base1 + col) = lo;
        }
    }
}

// ---------------------------------------------------------------------------
extern "C" void kernel_launch(void* const* d_in, const int* in_sizes, int n_in,
                              void* d_out, int out_size)
{
    (void)in_sizes; (void)n_in; (void)out_size;
    const float* x     = (const float*)d_in[0];
    const float* Wqkv  = (const float*)d_in[2];
    const float* bqkv  = (const float*)d_in[3];
    const float* Wproj = (const float*)d_in[4];
    const float* bproj = (const float*)d_in[5];
    float* out = (float*)d_out;

    void *ahi_p, *alo_p, *wq_hi_p, *wq_lo_p, *wp_hi_p, *wp_lo_p;
    cudaGetSymbolAddress(&ahi_p, g_Ahi);
    cudaGetSymbolAddress(&alo_p, g_Alo);
    cudaGetSymbolAddress(&wq_hi_p, g_Wqkv_hi);
    cudaGetSymbolAddress(&wq_lo_p, g_Wqkv_lo);
    cudaGetSymbolAddress(&wp_hi_p, g_Wproj_hi);
    cudaGetSymbolAddress(&wp_lo_p, g_Wproj_lo);
    __nv_bfloat16* Ahi = (__nv_bfloat16*)ahi_p;
    __nv_bfloat16* Alo = (__nv_bfloat16*)alo_p;
    __nv_bfloat16* WqH = (__nv_bfloat16*)wq_hi_p;
    __nv_bfloat16* WqL = (__nv_bfloat16*)wq_lo_p;
    __nv_bfloat16* WpH = (__nv_bfloat16*)wp_hi_p;
    __nv_bfloat16* WpL = (__nv_bfloat16*)wp_lo_p;

    cudaFuncSetAttribute(gemm_bf16x3_kernel,
                         cudaFuncAttributeMaxDynamicSharedMemorySize, GB_SMEM);
    cudaFuncSetAttribute(flash_attn_mma_kernel,
                         cudaFuncAttributeMaxDynamicSharedMemorySize, FA_SMEM);

    const int M = BATCH * SEQ;               // 4096
    const int nelem = M * D_MODEL;

    // 0) RoPE cos/sin table
    rope_table_kernel<<<SEQ * 64 / 256, 256>>>();

    // 1) split activations x -> (Ahi, Alo)
    split_kernel<<<(nelem / 4 + 255) / 256, 256>>>(x, Ahi, Alo, nelem / 4);

    // 2) weight transpose + split
    transpose_split_kernel<<<dim3(3 * D_MODEL / 64, D_MODEL / 64), 256>>>(
        Wqkv, WqH, WqL, D_MODEL, 3 * D_MODEL);
    transpose_split_kernel<<<dim3(D_MODEL / 64, D_MODEL / 64), 256>>>(
        Wproj, WpH, WpL, D_MODEL, D_MODEL);

    // 3) QKV projection with FUSED rope/split epilogue (3-stage, 1 sync/iter)
    gemm_bf16x3_kernel<<<dim3(3 * D_MODEL / 128, M / 128), 128, GB_SMEM>>>(
        Ahi, Alo, WqH, WqL, bqkv, nullptr, M, 3 * D_MODEL, D_MODEL, 1);

    // 4) MMA flash attention: 4 warps x 32 rows, halved K/V smem redundancy
    flash_attn_mma_kernel<<<dim3(SEQ / FA_TQ, BATCH * N_HEAD), 128, FA_SMEM>>>();

    // 5) output projection (plain epilogue)
    gemm_bf16x3_kernel<<<dim3(D_MODEL / 128, M / 128), 128, GB_SMEM>>>(
        Ahi, Alo, WpH, WpL, bproj, out, M, D_MODEL, D_MODEL, 0);
}

// round 15
// speedup vs baseline: 1.2278x; 1.2278x over previous
#include <cuda_runtime.h>
#include <cuda_bf16.h>
#include <cuda_fp16.h>
#include <math.h>
#include <stdint.h>

#define D_MODEL 2048
#define N_HEAD  16
#define HEAD_DIM 128
#define BATCH   2
#define SEQ     2048

// ---------------------------------------------------------------------------
// Static scratch (no cudaMalloc anywhere)
// ---------------------------------------------------------------------------
static __device__ float g_rope[(size_t)SEQ * 128];                // cos/sin table
static __device__ __nv_bfloat16 g_Ahi[(size_t)BATCH * SEQ * D_MODEL];  // attn out hi
static __device__ __nv_bfloat16 g_Alo[(size_t)BATCH * SEQ * D_MODEL];  // attn out lo
static __device__ __half g_Xhi[(size_t)BATCH * SEQ * D_MODEL];         // x fp16 hi
static __device__ __half g_Xlo[(size_t)BATCH * SEQ * D_MODEL];         // x fp16 lo
static __device__ __half g_Wqkv16[(size_t)3 * D_MODEL * D_MODEL];      // [N][K] fp16
static __device__ __nv_bfloat16 g_Wproj_hi[(size_t)D_MODEL * D_MODEL];
static __device__ __nv_bfloat16 g_Wproj_lo[(size_t)D_MODEL * D_MODEL];
// head-major prepped attention operands: [b][h][t][d]
static __device__ __nv_bfloat16 g_Qhi[(size_t)BATCH * SEQ * D_MODEL];
static __device__ __nv_bfloat16 g_Qlo[(size_t)BATCH * SEQ * D_MODEL];
static __device__ __nv_bfloat16 g_Khi[(size_t)BATCH * SEQ * D_MODEL];
static __device__ __nv_bfloat16 g_Klo[(size_t)BATCH * SEQ * D_MODEL];
static __device__ __nv_bfloat16 g_Vhi[(size_t)BATCH * SEQ * D_MODEL];
static __device__ __nv_bfloat16 g_Vlo[(size_t)BATCH * SEQ * D_MODEL];

// ---------------------------------------------------------------------------
// PTX helpers (sm_80+ subset: cp.async / ldmatrix / mma.sync)
// ---------------------------------------------------------------------------
__device__ __forceinline__ uint32_t smem_to_u32(const void* smem_ptr) {
    uint32_t addr;
    asm("{ .reg .u64 tmp; cvta.to.shared.u64 tmp, %1; cvt.u32.u64 %0, tmp; }"
        : "=r"(addr) : "l"(smem_ptr));
    return addr;
}

__device__ __forceinline__ void cp_async16(uint32_t smem_dst, const void* gmem_src) {
    asm volatile("cp.async.cg.shared.global.L2::128B [%0], [%1], 16;"
                 :: "r"(smem_dst), "l"(__cvta_generic_to_global(gmem_src)));
}
#define CP_ASYNC_COMMIT() asm volatile("cp.async.commit_group;" ::: "memory")
#define CP_ASYNC_WAIT_1() asm volatile("cp.async.wait_group 1;" ::: "memory")
#define CP_ASYNC_WAIT_2() asm volatile("cp.async.wait_group 2;" ::: "memory")

__device__ __forceinline__ void ldsm4(uint32_t* r, uint32_t addr) {
    asm volatile("ldmatrix.sync.aligned.m8n8.x4.shared.b16 {%0,%1,%2,%3}, [%4];"
                 : "=r"(r[0]), "=r"(r[1]), "=r"(r[2]), "=r"(r[3]) : "r"(addr));
}
__device__ __forceinline__ void ldsm4t(uint32_t* r, uint32_t addr) {
    asm volatile("ldmatrix.sync.aligned.m8n8.x4.trans.shared.b16 {%0,%1,%2,%3}, [%4];"
                 : "=r"(r[0]), "=r"(r[1]), "=r"(r[2]), "=r"(r[3]) : "r"(addr));
}

__device__ __forceinline__ void mma_bf16(float* c, const uint32_t* a,
                                         uint32_t b0, uint32_t b1) {
    asm volatile(
        "mma.sync.aligned.m16n8k16.row.col.f32.bf16.bf16.f32 "
        "{%0,%1,%2,%3}, {%4,%5,%6,%7}, {%8,%9}, {%0,%1,%2,%3};"
        : "+f"(c[0]), "+f"(c[1]), "+f"(c[2]), "+f"(c[3])
        : "r"(a[0]), "r"(a[1]), "r"(a[2]), "r"(a[3]), "r"(b0), "r"(b1));
}
__device__ __forceinline__ void mma_f16(float* c, const uint32_t* a,
                                        uint32_t b0, uint32_t b1) {
    asm volatile(
        "mma.sync.aligned.m16n8k16.row.col.f32.f16.f16.f32 "
        "{%0,%1,%2,%3}, {%4,%5,%6,%7}, {%8,%9}, {%0,%1,%2,%3};"
        : "+f"(c[0]), "+f"(c[1]), "+f"(c[2]), "+f"(c[3])
        : "r"(a[0]), "r"(a[1]), "r"(a[2]), "r"(a[3]), "r"(b0), "r"(b1));
}

// pack (s0 -> low bf16, s1 -> high bf16) into hi; residuals into lo.
__device__ __forceinline__ void split2(float s0, float s1, uint32_t& hi, uint32_t& lo) {
    asm("cvt.rn.bf16x2.f32 %0, %1, %2;" : "=r"(hi) : "f"(s1), "f"(s0));
    __nv_bfloat162 hv = *reinterpret_cast<__nv_bfloat162*>(&hi);
    float r0 = s0 - __bfloat162float(hv.x);
    float r1 = s1 - __bfloat162float(hv.y);
    asm("cvt.rn.bf16x2.f32 %0, %1, %2;" : "=r"(lo) : "f"(r1), "f"(r0));
}

// ---------------------------------------------------------------------------
// RoPE table
// ---------------------------------------------------------------------------
__global__ void rope_table_kernel()
{
    const float RATE_C = 0.14391156831212787f; // ln(10000)/64
    int i = blockIdx.x * blockDim.x + threadIdx.x;  // t*64 + j
    int t = i >> 6, j = i & 63;
    float rate = expf(-RATE_C * (float)j);
    float sv, cv;
    sincosf((float)t * rate, &sv, &cv);
    g_rope[t * 128 + j]      = cv;
    g_rope[t * 128 + 64 + j] = sv;
}

// ---------------------------------------------------------------------------
// x fp32 -> (hi, lo) fp16 pair (for fp16x2 QKV GEMM A operand).
// ---------------------------------------------------------------------------
__global__ void split_f16_kernel(const float* __restrict__ X, int n4)
{
    int i = blockIdx.x * blockDim.x + threadIdx.x;
    if (i >= n4) return;
    float4 v = *(const float4*)(X + (size_t)i * 4);
    __half h[4], l[4];
    float vv[4] = {v.x, v.y, v.z, v.w};
#pragma unroll
    for (int j = 0; j < 4; ++j) {
        h[j] = __float2half_rn(vv[j]);
        l[j] = __float2half_rn(vv[j] - __half2float(h[j]));
    }
    *(uint2*)(g_Xhi + (size_t)i * 4) = *(uint2*)h;
    *(uint2*)(g_Xlo + (size_t)i * 4) = *(uint2*)l;
}

// ---------------------------------------------------------------------------
// Transpose: Wqkv[K,N] fp32 -> [N,K] fp16 (plain; residual dropped by design).
// ---------------------------------------------------------------------------
__global__ __launch_bounds__(256) void transpose_f16_kernel(
    const float* __restrict__ W, int K, int N)
{
    __shared__ float tile[64][65];
    const int k0 = blockIdx.y * 64;
    const int n0 = blockIdx.x * 64;
    const int tid = threadIdx.x;

#pragma unroll
    for (int j = 0; j < 4; ++j) {
        int idx = tid + j * 256;
        int r  = idx >> 4;
        int c4 = (idx & 15) * 4;
        float4 v = *(const float4*)(W + (size_t)(k0 + r) * N + n0 + c4);
        tile[r][c4 + 0] = v.x; tile[r][c4 + 1] = v.y;
        tile[r][c4 + 2] = v.z; tile[r][c4 + 3] = v.w;
    }
    __syncthreads();

    const int n  = tid >> 2;
    const int ks = (tid & 3) * 16;
    __half h[16];
#pragma unroll
    for (int j = 0; j < 16; ++j)
        h[j] = __float2half_rn(tile[ks + j][n]);
    size_t base = (size_t)(n0 + n) * K + k0 + ks;
    *(uint4*)(g_Wqkv16 + base)     = ((uint4*)h)[0];
    *(uint4*)(g_Wqkv16 + base + 8) = ((uint4*)h)[1];
}

// ---------------------------------------------------------------------------
// Transpose + split: Wproj[K,N] fp32 -> hi/lo [N,K] bf16 (for bf16x3 proj).
// ---------------------------------------------------------------------------
__global__ __launch_bounds__(256) void transpose_split_kernel(
    const float* __restrict__ W,
    __nv_bfloat16* __restrict__ Thi, __nv_bfloat16* __restrict__ Tlo,
    int K, int N)
{
    __shared__ float tile[64][65];
    const int k0 = blockIdx.y * 64;
    const int n0 = blockIdx.x * 64;
    const int tid = threadIdx.x;

#pragma unroll
    for (int j = 0; j < 4; ++j) {
        int idx = tid + j * 256;
        int r  = idx >> 4;
        int c4 = (idx & 15) * 4;
        float4 v = *(const float4*)(W + (size_t)(k0 + r) * N + n0 + c4);
        tile[r][c4 + 0] = v.x; tile[r][c4 + 1] = v.y;
        tile[r][c4 + 2] = v.z; tile[r][c4 + 3] = v.w;
    }
    __syncthreads();

    const int n  = tid >> 2;
    const int ks = (tid & 3) * 16;
    __nv_bfloat16 h[16], l[16];
#pragma unroll
    for (int j = 0; j < 16; ++j) {
        float v = tile[ks + j][n];
        h[j] = __float2bfloat16(v);
        l[j] = __float2bfloat16(v - __bfloat162float(h[j]));
    }
    size_t base = (size_t)(n0 + n) * K + k0 + ks;
    *(uint4*)(Thi + base)     = ((uint4*)h)[0];
    *(uint4*)(Thi + base + 8) = ((uint4*)h)[1];
    *(uint4*)(Tlo + base)     = ((uint4*)l)[0];
    *(uint4*)(Tlo + base + 8) = ((uint4*)l)[1];
}

// ---------------------------------------------------------------------------
// Templated HMMA GEMM (R9 pipeline): 4 warps 2x2, 64x64 warp tiles, 3-stage
// XOR-swizzled cp.async, 1 barrier/iter, 2 CTAs/SM.
// MODE 0: bf16x3  (A hi/lo, B hi/lo, 3 MMAs/frag)
// MODE 1: fp16x2  (A hi/lo, B hi only, 2 MMAs/frag; B-lo slot unused)
// fuse_qkv == 1: QKV epilogue (rope/scale/split, head-major bf16 hi/lo out).
// ---------------------------------------------------------------------------
#define GB_OP     (128 * 64)                // 8192 B per operand tile
#define GB_STAGE  (4 * GB_OP)               // 32768 B
#define GB_NSTAGE 3
#define GB_SMEM   (GB_NSTAGE * GB_STAGE)    // 98304 B (>= 128*132*4 = 67584)

#define GB_SWIZ(row, c) ((uint32_t)((row) * 64 + (((c) ^ (((row) >> 1) & 3)) * 16)))

template<int MODE>
__device__ __forceinline__ void gemm_load_stage(
    uint32_t st,
    const uint16_t* __restrict__ Ahi, const uint16_t* __restrict__ Alo,
    const uint16_t* __restrict__ Bhi, const uint16_t* __restrict__ Blo,
    int bm, int bn, int k0, int K, int tid)
{
#pragma unroll
    for (int j = 0; j < 4; ++j) {
        int idx = tid + j * 128;            // 0..511
        int row = idx >> 2;                 // 0..127
        int c   = idx & 3;                  // 16B chunk within 64B row
        uint32_t off = GB_SWIZ(row, c);
        size_t ga = (size_t)(bm + row) * K + k0 + c * 8;
        size_t gb = (size_t)(bn + row) * K + k0 + c * 8;
        cp_async16(st + off,              Ahi + ga);
        cp_async16(st + GB_OP + off,      Alo + ga);
        cp_async16(st + 2 * GB_OP + off,  Bhi + gb);
        if (MODE == 0)
            cp_async16(st + 3 * GB_OP + off, Blo + gb);
    }
}

template<int MODE>
__global__ __launch_bounds__(128, 2) void gemm_kernel(
    const uint16_t* __restrict__ Ahi, const uint16_t* __restrict__ Alo,
    const uint16_t* __restrict__ Bhi, const uint16_t* __restrict__ Blo,
    const float* __restrict__ bias, float* __restrict__ C,
    int M, int N, int K, int fuse_qkv)
{
    extern __shared__ __align__(128) char smem[];
    const uint32_t sbase = smem_to_u32(smem);
    const int tid  = threadIdx.x;
    const int lane = tid & 31;
    const int wid  = tid >> 5;              // 0..3
    const int wm   = wid >> 1;              // 0..1 (64-row stripes)
    const int wn   = wid & 1;               // 0..1 (64-col stripes)
    const int bm   = blockIdx.y * 128;
    const int bn   = blockIdx.x * 128;

    float acc[4][8][4];
#pragma unroll
    for (int mi = 0; mi < 4; ++mi)
#pragma unroll
        for (int ni = 0; ni < 8; ++ni)
#pragma unroll
            for (int r = 0; r < 4; ++r) acc[mi][ni][r] = 0.f;

    const int nk = K / 32;

    gemm_load_stage<MODE>(sbase,            Ahi, Alo, Bhi, Blo, bm, bn, 0,  K, tid);
    CP_ASYNC_COMMIT();
    gemm_load_stage<MODE>(sbase + GB_STAGE, Ahi, Alo, Bhi, Blo, bm, bn, 32, K, tid);
    CP_ASYNC_COMMIT();

    const int lrowA = lane & 15, lcolA = lane >> 4;
    const int bg    = lane >> 3, blr  = lane & 7;

    for (int i = 0; i < nk; ++i) {
        const uint32_t st = sbase + (uint32_t)(i % GB_NSTAGE) * GB_STAGE;
        CP_ASYNC_WAIT_1();
        __syncthreads();

        if (i + 2 < nk) {
            gemm_load_stage<MODE>(sbase + (uint32_t)((i + 2) % GB_NSTAGE) * GB_STAGE,
                                  Ahi, Alo, Bhi, Blo, bm, bn, (i + 2) * 32, K, tid);
        }
        CP_ASYNC_COMMIT();

        const uint32_t aHi = st;
        const uint32_t aLo = st + GB_OP;
        const uint32_t bHi = st + 2 * GB_OP;
        const uint32_t bLo = st + 3 * GB_OP;

#pragma unroll
        for (int ks = 0; ks < 2; ++ks) {
            uint32_t ah[4][4], al[4][4];
#pragma unroll
            for (int mi = 0; mi < 4; ++mi) {
                int row = wm * 64 + mi * 16 + lrowA;
                uint32_t off = GB_SWIZ(row, ks * 2 + lcolA);
                ldsm4(ah[mi], aHi + off);
                ldsm4(al[mi], aLo + off);
            }
#pragma unroll
            for (int np = 0; np < 4; ++np) {
                uint32_t bh[4], bl[4];
                int row = wn * 64 + np * 16 + (bg >> 1) * 8 + blr;
                uint32_t off = GB_SWIZ(row, ks * 2 + (bg & 1));
                ldsm4(bh, bHi + off);
                if (MODE == 0) ldsm4(bl, bLo + off);
#pragma unroll
                for (int mi = 0; mi < 4; ++mi)
#pragma unroll
                    for (int q = 0; q < 2; ++q) {
                        int ni = np * 2 + q, pr = q * 2;
                        if (MODE == 0) {
                            mma_bf16(acc[mi][ni], ah[mi], bh[pr], bh[pr + 1]);
                            mma_bf16(acc[mi][ni], ah[mi], bl[pr], bl[pr + 1]);
                            mma_bf16(acc[mi][ni], al[mi], bh[pr], bh[pr + 1]);
                        } else {
                            mma_f16(acc[mi][ni], ah[mi], bh[pr], bh[pr + 1]);
                            mma_f16(acc[mi][ni], al[mi], bh[pr], bh[pr + 1]);
                        }
                    }
            }
        }
    }

    const int gid = lane >> 2, tig = lane & 3;

    if (fuse_qkv == 0) {
#pragma unroll
        for (int mi = 0; mi < 4; ++mi)
#pragma unroll
            for (int ni = 0; ni < 8; ++ni) {
                int row = bm + wm * 64 + mi * 16 + gid;
                int col = bn + wn * 64 + ni * 8 + tig * 2;
                float2 bv = *(const float2*)(bias + col);
                float2 v0 = make_float2(acc[mi][ni][0] + bv.x, acc[mi][ni][1] + bv.y);
                float2 v1 = make_float2(acc[mi][ni][2] + bv.x, acc[mi][ni][3] + bv.y);
                *(float2*)(C + (size_t)row * N + col)       = v0;
                *(float2*)(C + (size_t)(row + 8) * N + col) = v1;
            }
        return;
    }

    // ---- fused QKV epilogue: rope/scale/split, head-major bf16 hi/lo ----
    __syncthreads();
    float* Cs = (float*)smem;                 // 128 x 132 fp32, reuses stages
#pragma unroll
    for (int mi = 0; mi < 4; ++mi)
#pragma unroll
        for (int ni = 0; ni < 8; ++ni) {
            int row = wm * 64 + mi * 16 + gid;
            int col = wn * 64 + ni * 8 + tig * 2;
            float2 bv = *(const float2*)(bias + bn + col);
            Cs[row * 132 + col]           = acc[mi][ni][0] + bv.x;
            Cs[row * 132 + col + 1]       = acc[mi][ni][1] + bv.y;
            Cs[(row + 8) * 132 + col]     = acc[mi][ni][2] + bv.x;
            Cs[(row + 8) * 132 + col + 1] = acc[mi][ni][3] + bv.y;
        }
    __syncthreads();

    const int sel = bn >> 11;                 // 0=Q, 1=K, 2=V
    const int hh  = (bn & 2047) >> 7;         // head
    __nv_bfloat16 *dh, *dl;
    if (sel == 0)      { dh = g_Qhi; dl = g_Qlo; }
    else if (sel == 1) { dh = g_Khi; dl = g_Klo; }
    else               { dh = g_Vhi; dl = g_Vlo; }
    const float SCALE = 0.08838834764831845f; // 1/sqrt(128)

    for (int i = tid; i < 128 * 32; i += 128) {
        int row = i >> 5, jp = (i & 31) * 2;
        int tg = bm + row, t = tg & (SEQ - 1), bb = tg >> 11;
        float x1a = Cs[row * 132 + jp],      x1b = Cs[row * 132 + jp + 1];
        float x2a = Cs[row * 132 + jp + 64], x2b = Cs[row * 132 + jp + 65];
        float y1a, y1b, y2a, y2b;
        if (sel < 2) {
            float cva = g_rope[t * 128 + jp],     sva = g_rope[t * 128 + 64 + jp];
            float cvb = g_rope[t * 128 + jp + 1], svb = g_rope[t * 128 + 64 + jp + 1];
            y1a = x1a * cva - x2a * sva;  y2a = x1a * sva + x2a * cva;
            y1b = x1b * cvb - x2b * svb;  y2b = x1b * svb + x2b * cvb;
            if (sel == 0) { y1a *= SCALE; y2a *= SCALE; y1b *= SCALE; y2b *= SCALE; }
        } else {
            y1a = x1a; y1b = x1b; y2a = x2a; y2b = x2b;
        }
        size_t base = ((size_t)(bb * N_HEAD + hh) * SEQ + t) * HEAD_DIM;
        uint32_t hi, lo;
        split2(y1a, y1b, hi, lo);
        *(uint32_t*)(dh + base + jp)      = hi;
        *(uint32_t*)(dl + base + jp)      = lo;
        split2(y2a, y2b, hi, lo);
        *(uint32_t*)(dh + base + jp + 64) = hi;
        *(uint32_t*)(dl + base + jp + 64) = lo;
    }
}

// ---------------------------------------------------------------------------
// MMA flash attention (R12 best-known): Q in regs, tri-buffered KV,
// ONE __syncthreads per K-tile, prefetch before MMA.
// ---------------------------------------------------------------------------
#define FA_TQ 128
#define FA_TK 64
#define FA_ROWB 272
#define FA_BUF  69632                 // KV buffer: KHI +0, KLO +17408, VHI +34816, VLO +52224
#define FA_SMEM (3 * FA_BUF)          // 208896; Q staged in buf2 then recycled

__device__ __forceinline__ void fa_load_kv(uint32_t buf, size_t bh_elem, int k0, int tid)
{
    size_t gbase = bh_elem + (size_t)k0 * HEAD_DIM;
    for (int i = tid; i < FA_TK * 16; i += 256) {
        int row = i >> 4, c = i & 15;
        uint32_t soff = (uint32_t)(row * FA_ROWB + c * 16);
        size_t   goff = gbase + (size_t)row * HEAD_DIM + c * 8;
        cp_async16(buf + soff,         g_Khi + goff);
        cp_async16(buf + 17408 + soff, g_Klo + goff);
        cp_async16(buf + 34816 + soff, g_Vhi + goff);
        cp_async16(buf + 52224 + soff, g_Vlo + goff);
    }
}

__global__ __launch_bounds__(256, 1) void flash_attn_mma_kernel()
{
    extern __shared__ __align__(128) char sm[];
    const uint32_t sbase = smem_to_u32(sm);

    const int tid  = threadIdx.x;
    const int lane = tid & 31;
    const int wid  = tid >> 5;
    const int qt   = (gridDim.x - 1) - blockIdx.x;   // heavy tiles first
    const int q0   = qt * FA_TQ;
    const int b    = blockIdx.y >> 4;
    const int h    = blockIdx.y & 15;

    const size_t bh_elem = (size_t)(b * N_HEAD + h) * SEQ * HEAD_DIM;
    const int ktmax = 2 * qt + 1;                    // >= 1 always

    // ---- prologue loads: Q -> buf2 region (g0), KV0 (g1), KV1 (g2) ----
    {
        size_t qbase = bh_elem + (size_t)q0 * HEAD_DIM;
        const uint32_t qarea = sbase + 2 * FA_BUF;   // QHI +0, QLO +34816
        for (int i = tid; i < FA_TQ * 16; i += 256) {
            int row = i >> 4, c = i & 15;
            uint32_t soff = (uint32_t)(row * FA_ROWB + c * 16);
            size_t   goff = qbase + (size_t)row * HEAD_DIM + c * 8;
            cp_async16(qarea + soff,         g_Qhi + goff);
            cp_async16(qarea + 34816 + soff, g_Qlo + goff);
        }
    }
    CP_ASYNC_COMMIT();                               // g0: Q
    fa_load_kv(sbase, bh_elem, 0, tid);
    CP_ASYNC_COMMIT();                               // g1: KV0
    fa_load_kv(sbase + FA_BUF, bh_elem, FA_TK, tid);
    CP_ASYNC_COMMIT();                               // g2: KV1

    const int gid = lane >> 2, tig = lane & 3;
    const int lrowA = lane & 15, lcolA = lane >> 4;
    const int bg = lane >> 3, blr = lane & 7;
    const int wrow_lo = q0 + wid * 16;

    // ---- hoist Q into registers (then buf2 is recycled as KV buffer) ----
    uint32_t qh[8][4], ql[8][4];
    CP_ASYNC_WAIT_2();              // g0 (Q) complete
    __syncthreads();
    {
        const uint32_t qarea = sbase + 2 * FA_BUF;
#pragma unroll
        for (int ks = 0; ks < 8; ++ks) {
            uint32_t qoff = (uint32_t)((wid * 16 + lrowA) * FA_ROWB
                                       + (ks * 16 + lcolA * 8) * 2);
            ldsm4(qh[ks], qarea + qoff);
            ldsm4(ql[ks], qarea + 34816 + qoff);
        }
    }
    __syncthreads();                // Q reads done -> buf2 free for KV2

    float oacc[16][4];
#pragma unroll
    for (int ni = 0; ni < 16; ++ni)
#pragma unroll
        for (int r = 0; r < 4; ++r) oacc[ni][r] = 0.f;
    float m0 = -1e30f, m1 = -1e30f, l0 = 0.f, l1 = 0.f;

    for (int kt = 0; kt <= ktmax; ++kt) {
        const int k0 = kt * FA_TK;
        const uint32_t buf = sbase + (uint32_t)(kt % 3) * FA_BUF;
        CP_ASYNC_WAIT_1();          // KV[kt] resident; KV[kt+1] may pend
        __syncthreads();            // data visible + prior-iter buffer reads done

        // prefetch KV[kt+2] into buf (kt+2)%3 (consumed at iter kt-1) -> overlaps MMA
        if (kt + 2 <= ktmax)
            fa_load_kv(sbase + (uint32_t)((kt + 2) % 3) * FA_BUF,
                       bh_elem, (kt + 2) * FA_TK, tid);
        CP_ASYNC_COMMIT();

        if (k0 <= wrow_lo + 15) {   // warp-level causal skip
            // ---- S = Q(regs) @ K^T, bf16x3 ----
            float sacc[8][4];
#pragma unroll
            for (int ni = 0; ni < 8; ++ni)
#pragma unroll
                for (int r = 0; r < 4; ++r) sacc[ni][r] = 0.f;

#pragma unroll
            for (int ks = 0; ks < 8; ++ks) {
#pragma unroll
                for (int np = 0; np < 4; ++np) {
                    uint32_t kh[4], kl[4];
                    uint32_t koff = (uint32_t)((np * 16 + (bg >> 1) * 8 + blr) * FA_ROWB
                                               + (ks * 16 + (bg & 1) * 8) * 2);
                    ldsm4(kh, buf + koff);
                    ldsm4(kl, buf + 17408 + koff);
#pragma unroll
                    for (int q = 0; q < 2; ++q) {
                        int ni = np * 2 + q, pr = q * 2;
                        mma_bf16(sacc[ni], qh[ks], kh[pr], kh[pr + 1]);
                        mma_bf16(sacc[ni], qh[ks], kl[pr], kl[pr + 1]);
                        mma_bf16(sacc[ni], ql[ks], kh[pr], kh[pr + 1]);
                    }
                }
            }

            // ---- causal mask (partial tiles only) ----
            const int row0 = wrow_lo + gid, row1 = row0 + 8;
            if (k0 + FA_TK - 1 > q0) {
#pragma unroll
                for (int ni = 0; ni < 8; ++ni) {
                    int col = k0 + ni * 8 + tig * 2;
                    if (col     > row0) sacc[ni][0] = -1e30f;
                    if (col + 1 > row0) sacc[ni][1] = -1e30f;
                    if (col     > row1) sacc[ni][2] = -1e30f;
                    if (col + 1 > row1) sacc[ni][3] = -1e30f;
                }
            }

            // ---- online softmax ----
            float mx0 = -1e30f, mx1 = -1e30f;
#pragma unroll
            for (int ni = 0; ni < 8; ++ni) {
                mx0 = fmaxf(mx0, fmaxf(sacc[ni][0], sacc[ni][1]));
                mx1 = fmaxf(mx1, fmaxf(sacc[ni][2], sacc[ni][3]));
            }
#pragma unroll
            for (int off = 1; off < 4; off <<= 1) {
                mx0 = fmaxf(mx0, __shfl_xor_sync(0xffffffffu, mx0, off));
                mx1 = fmaxf(mx1, __shfl_xor_sync(0xffffffffu, mx1, off));
            }
            float mn0 = fmaxf(m0, mx0), mn1 = fmaxf(m1, mx1);
            float a0 = __expf(m0 - mn0), a1 = __expf(m1 - mn1);
            m0 = mn0; m1 = mn1;
            float sum0 = 0.f, sum1 = 0.f;
#pragma unroll
            for (int ni = 0; ni < 8; ++ni) {
                sacc[ni][0] = __expf(sacc[ni][0] - mn0);
                sacc[ni][1] = __expf(sacc[ni][1] - mn0);
                sacc[ni][2] = __expf(sacc[ni][2] - mn1);
                sacc[ni][3] = __expf(sacc[ni][3] - mn1);
                sum0 += sacc[ni][0] + sacc[ni][1];
                sum1 += sacc[ni][2] + sacc[ni][3];
            }
#pragma unroll
            for (int off = 1; off < 4; off <<= 1) {
                sum0 += __shfl_xor_sync(0xffffffffu, sum0, off);
                sum1 += __shfl_xor_sync(0xffffffffu, sum1, off);
            }
            l0 = l0 * a0 + sum0;
            l1 = l1 * a1 + sum1;
#pragma unroll
            for (int ni = 0; ni < 16; ++ni) {
                oacc[ni][0] *= a0; oacc[ni][1] *= a0;
                oacc[ni][2] *= a1; oacc[ni][3] *= a1;
            }

            // ---- O += P @ V, bf16x3 (V via trans ldmatrix) ----
            const uint32_t vhi = buf + 34816, vlo = buf + 52224;
#pragma unroll
            for (int kc = 0; kc < 4; ++kc) {
                uint32_t ah[4], al[4];
                split2(sacc[2 * kc][0],     sacc[2 * kc][1],     ah[0], al[0]);
                split2(sacc[2 * kc][2],     sacc[2 * kc][3],     ah[1], al[1]);
                split2(sacc[2 * kc + 1][0], sacc[2 * kc + 1][1], ah[2], al[2]);
                split2(sacc[2 * kc + 1][2], sacc[2 * kc + 1][3], ah[3], al[3]);
#pragma unroll
                for (int np = 0; np < 8; ++np) {
                    uint32_t vh[4], vl[4];
                    uint32_t voff = (uint32_t)((kc * 16 + (lane & 15)) * FA_ROWB
                                               + (np * 16 + (lane >> 4) * 8) * 2);
                    ldsm4t(vh, vhi + voff);
                    ldsm4t(vl, vlo + voff);
#pragma unroll
                    for (int q = 0; q < 2; ++q) {
                        int ni = np * 2 + q, pr = q * 2;
                        mma_bf16(oacc[ni], ah, vh[pr], vh[pr + 1]);
                        mma_bf16(oacc[ni], ah, vl[pr], vl[pr + 1]);
                        mma_bf16(oacc[ni], al, vh[pr], vh[pr + 1]);
                    }
                }
            }
        }
    }

    // ---- epilogue: normalize, split to bf16 hi/lo, store ----
    {
        float inv0 = 1.f / l0, inv1 = 1.f / l1;
        int t0 = wrow_lo + gid;
        size_t base0 = (size_t)(b * SEQ + t0) * D_MODEL + h * HEAD_DIM;
        size_t base1 = (size_t)(b * SEQ + t0 + 8) * D_MODEL + h * HEAD_DIM;
#pragma unroll
        for (int ni = 0; ni < 16; ++ni) {
            int col = ni * 8 + tig * 2;
            uint32_t hi, lo;
            split2(oacc[ni][0] * inv0, oacc[ni][1] * inv0, hi, lo);
            *(uint32_t*)(g_Ahi + base0 + col) = hi;
            *(uint32_t*)(g_Alo + base0 + col) = lo;
            split2(oacc[ni][2] * inv1, oacc[ni][3] * inv1, hi, lo);
            *(uint32_t*)(g_Ahi + base1 + col) = hi;
            *(uint32_t*)(g_Alo + base1 + col) = lo;
        }
    }
}

// ---------------------------------------------------------------------------
extern "C" void kernel_launch(void* const* d_in, const int* in_sizes, int n_in,
                              void* d_out, int out_size)
{
    (void)in_sizes; (void)n_in; (void)out_size;
    const float* x     = (const float*)d_in[0];
    const float* Wqkv  = (const float*)d_in[2];
    const float* bqkv  = (const float*)d_in[3];
    const float* Wproj = (const float*)d_in[4];
    const float* bproj = (const float*)d_in[5];
    float* out = (float*)d_out;

    void *ahi_p, *alo_p, *xhi_p, *xlo_p, *wq16_p, *wp_hi_p, *wp_lo_p;
    cudaGetSymbolAddress(&ahi_p, g_Ahi);
    cudaGetSymbolAddress(&alo_p, g_Alo);
    cudaGetSymbolAddress(&xhi_p, g_Xhi);
    cudaGetSymbolAddress(&xlo_p, g_Xlo);
    cudaGetSymbolAddress(&wq16_p, g_Wqkv16);
    cudaGetSymbolAddress(&wp_hi_p, g_Wproj_hi);
    cudaGetSymbolAddress(&wp_lo_p, g_Wproj_lo);

    cudaFuncSetAttribute(gemm_kernel<0>,
                         cudaFuncAttributeMaxDynamicSharedMemorySize, GB_SMEM);
    cudaFuncSetAttribute(gemm_kernel<1>,
                         cudaFuncAttributeMaxDynamicSharedMemorySize, GB_SMEM);
    cudaFuncSetAttribute(flash_attn_mma_kernel,
                         cudaFuncAttributeMaxDynamicSharedMemorySize, FA_SMEM);

    const int M = BATCH * SEQ;               // 4096
    const int nelem = M * D_MODEL;

    // 0) RoPE cos/sin table
    rope_table_kernel<<<SEQ * 64 / 256, 256>>>();

    // 1) split activations x -> fp16 (hi, lo)
    split_f16_kernel<<<(nelem / 4 + 255) / 256, 256>>>(x, nelem / 4);

    // 2) weight prep: Wqkv -> [N][K] fp16 (plain); Wproj -> bf16 hi/lo
    transpose_f16_kernel<<<dim3(3 * D_MODEL / 64, D_MODEL / 64), 256>>>(
        Wqkv, D_MODEL, 3 * D_MODEL);
    transpose_split_kernel<<<dim3(D_MODEL / 64, D_MODEL / 64), 256>>>(
        Wproj, (__nv_bfloat16*)wp_hi_p, (__nv_bfloat16*)wp_lo_p, D_MODEL, D_MODEL);

    // 3) QKV projection, fp16x2 (2 MMAs/frag), fused rope/split epilogue
    gemm_kernel<1><<<dim3(3 * D_MODEL / 128, M / 128), 128, GB_SMEM>>>(
        (const uint16_t*)xhi_p, (const uint16_t*)xlo_p,
        (const uint16_t*)wq16_p, nullptr,
        bqkv, nullptr, M, 3 * D_MODEL, D_MODEL, 1);

    // 4) MMA flash attention (R12 best-known: Q regs, tri-buffer)
    flash_attn_mma_kernel<<<dim3(SEQ / FA_TQ, BATCH * N_HEAD), 256, FA_SMEM>>>();

    // 5) output projection, bf16x3 (plain epilogue)
    gemm_kernel<0><<<dim3(D_MODEL / 128, M / 128), 128, GB_SMEM>>>(
        (const uint16_t*)ahi_p, (const uint16_t*)alo_p,
        (const uint16_t*)wp_hi_p, (const uint16_t*)wp_lo_p,
        bproj, out, M, D_MODEL, D_MODEL, 0);
}

// round 16
// speedup vs baseline: 1.4510x; 1.1818x over previous
#include <cuda_runtime.h>
#include <cuda_fp16.h>
#include <math.h>
#include <stdint.h>

#define D_MODEL 2048
#define N_HEAD  16
#define HEAD_DIM 128
#define BATCH   2
#define SEQ     2048

// ---------------------------------------------------------------------------
// Static scratch (no cudaMalloc anywhere) — all-fp16 pipeline
// ---------------------------------------------------------------------------
static __device__ float g_rope[(size_t)SEQ * 128];                // cos/sin table
static __device__ __half g_Xhi[(size_t)BATCH * SEQ * D_MODEL];    // x fp16 hi
static __device__ __half g_Xlo[(size_t)BATCH * SEQ * D_MODEL];    // x fp16 lo
static __device__ __half g_Wqkv16[(size_t)3 * D_MODEL * D_MODEL]; // [N][K] fp16
static __device__ __half g_Wproj16[(size_t)D_MODEL * D_MODEL];    // [N][K] fp16
static __device__ __half g_Ahi[(size_t)BATCH * SEQ * D_MODEL];    // attn out hi
static __device__ __half g_Alo[(size_t)BATCH * SEQ * D_MODEL];    // attn out lo
// head-major prepped attention operands: [b][h][t][d]
static __device__ __half g_Qhi[(size_t)BATCH * SEQ * D_MODEL];
static __device__ __half g_Qlo[(size_t)BATCH * SEQ * D_MODEL];
static __device__ __half g_K16[(size_t)BATCH * SEQ * D_MODEL];    // K plain fp16
static __device__ __half g_Vhi[(size_t)BATCH * SEQ * D_MODEL];
static __device__ __half g_Vlo[(size_t)BATCH * SEQ * D_MODEL];

// ---------------------------------------------------------------------------
// PTX helpers (sm_80+ subset: cp.async / ldmatrix / mma.sync)
// ---------------------------------------------------------------------------
__device__ __forceinline__ uint32_t smem_to_u32(const void* smem_ptr) {
    uint32_t addr;
    asm("{ .reg .u64 tmp; cvta.to.shared.u64 tmp, %1; cvt.u32.u64 %0, tmp; }"
        : "=r"(addr) : "l"(smem_ptr));
    return addr;
}

__device__ __forceinline__ void cp_async16(uint32_t smem_dst, const void* gmem_src) {
    asm volatile("cp.async.cg.shared.global.L2::128B [%0], [%1], 16;"
                 :: "r"(smem_dst), "l"(__cvta_generic_to_global(gmem_src)));
}
#define CP_ASYNC_COMMIT() asm volatile("cp.async.commit_group;" ::: "memory")
#define CP_ASYNC_WAIT_1() asm volatile("cp.async.wait_group 1;" ::: "memory")
#define CP_ASYNC_WAIT_2() asm volatile("cp.async.wait_group 2;" ::: "memory")

__device__ __forceinline__ void ldsm4(uint32_t* r, uint32_t addr) {
    asm volatile("ldmatrix.sync.aligned.m8n8.x4.shared.b16 {%0,%1,%2,%3}, [%4];"
                 : "=r"(r[0]), "=r"(r[1]), "=r"(r[2]), "=r"(r[3]) : "r"(addr));
}
__device__ __forceinline__ void ldsm4t(uint32_t* r, uint32_t addr) {
    asm volatile("ldmatrix.sync.aligned.m8n8.x4.trans.shared.b16 {%0,%1,%2,%3}, [%4];"
                 : "=r"(r[0]), "=r"(r[1]), "=r"(r[2]), "=r"(r[3]) : "r"(addr));
}

__device__ __forceinline__ void mma_f16(float* c, const uint32_t* a,
                                        uint32_t b0, uint32_t b1) {
    asm volatile(
        "mma.sync.aligned.m16n8k16.row.col.f32.f16.f16.f32 "
        "{%0,%1,%2,%3}, {%4,%5,%6,%7}, {%8,%9}, {%0,%1,%2,%3};"
        : "+f"(c[0]), "+f"(c[1]), "+f"(c[2]), "+f"(c[3])
        : "r"(a[0]), "r"(a[1]), "r"(a[2]), "r"(a[3]), "r"(b0), "r"(b1));
}

// pack (s0 -> low fp16, s1 -> high fp16); lo gets the residuals.
__device__ __forceinline__ void split2h(float s0, float s1, uint32_t& hi, uint32_t& lo) {
    asm("cvt.rn.f16x2.f32 %0, %1, %2;" : "=r"(hi) : "f"(s1), "f"(s0));
    __half2 hv = *reinterpret_cast<__half2*>(&hi);
    float r0 = s0 - __half2float(hv.x);
    float r1 = s1 - __half2float(hv.y);
    asm("cvt.rn.f16x2.f32 %0, %1, %2;" : "=r"(lo) : "f"(r1), "f"(r0));
}
__device__ __forceinline__ uint32_t pack2h(float s0, float s1) {
    uint32_t h;
    asm("cvt.rn.f16x2.f32 %0, %1, %2;" : "=r"(h) : "f"(s1), "f"(s0));
    return h;
}

// ---------------------------------------------------------------------------
// RoPE table
// ---------------------------------------------------------------------------
__global__ void rope_table_kernel()
{
    const float RATE_C = 0.14391156831212787f; // ln(10000)/64
    int i = blockIdx.x * blockDim.x + threadIdx.x;  // t*64 + j
    int t = i >> 6, j = i & 63;
    float rate = expf(-RATE_C * (float)j);
    float sv, cv;
    sincosf((float)t * rate, &sv, &cv);
    g_rope[t * 128 + j]      = cv;
    g_rope[t * 128 + 64 + j] = sv;
}

// ---------------------------------------------------------------------------
// x fp32 -> (hi, lo) fp16 pair.
// ---------------------------------------------------------------------------
__global__ void split_f16_kernel(const float* __restrict__ X, int n4)
{
    int i = blockIdx.x * blockDim.x + threadIdx.x;
    if (i >= n4) return;
    float4 v = *(const float4*)(X + (size_t)i * 4);
    uint32_t h0, l0, h1, l1;
    split2h(v.x, v.y, h0, l0);
    split2h(v.z, v.w, h1, l1);
    *(uint2*)(g_Xhi + (size_t)i * 4) = make_uint2(h0, h1);
    *(uint2*)(g_Xlo + (size_t)i * 4) = make_uint2(l0, l1);
}

// ---------------------------------------------------------------------------
// Transpose: W[K,N] fp32 -> dst[N,K] fp16 (plain).
// ---------------------------------------------------------------------------
__global__ __launch_bounds__(256) void transpose_f16_kernel(
    const float* __restrict__ W, __half* __restrict__ dst, int K, int N)
{
    __shared__ float tile[64][65];
    const int k0 = blockIdx.y * 64;
    const int n0 = blockIdx.x * 64;
    const int tid = threadIdx.x;

#pragma unroll
    for (int j = 0; j < 4; ++j) {
        int idx = tid + j * 256;
        int r  = idx >> 4;
        int c4 = (idx & 15) * 4;
        float4 v = *(const float4*)(W + (size_t)(k0 + r) * N + n0 + c4);
        tile[r][c4 + 0] = v.x; tile[r][c4 + 1] = v.y;
        tile[r][c4 + 2] = v.z; tile[r][c4 + 3] = v.w;
    }
    __syncthreads();

    const int n  = tid >> 2;
    const int ks = (tid & 3) * 16;
    __half h[16];
#pragma unroll
    for (int j = 0; j < 16; ++j)
        h[j] = __float2half_rn(tile[ks + j][n]);
    size_t base = (size_t)(n0 + n) * K + k0 + ks;
    *(uint4*)(dst + base)     = ((uint4*)h)[0];
    *(uint4*)(dst + base + 8) = ((uint4*)h)[1];
}

// ---------------------------------------------------------------------------
// fp16x2 HMMA GEMM: C = (Ahi+Alo)[M,K] @ B16[N,K]^T + bias.
// 4 warps 2x2, 64x64 warp tiles, 3-stage XOR-swizzled cp.async (3 slots:
// Ahi, Alo, B), 1 barrier/iter, 2 CTAs/SM. 2 MMAs per fragment.
// fuse_qkv == 1: QKV epilogue (rope/scale -> fp16 Q hi/lo, K plain, V hi/lo).
// ---------------------------------------------------------------------------
#define GB_OP     (128 * 64)                // 8192 B per operand tile
#define GB_STAGE  (3 * GB_OP)               // 24576 B
#define GB_NSTAGE 3
#define GB_SMEM   (GB_NSTAGE * GB_STAGE)    // 73728 B (>= 128*132*4 = 67584)

#define GB_SWIZ(row, c) ((uint32_t)((row) * 64 + (((c) ^ (((row) >> 1) & 3)) * 16)))

__device__ __forceinline__ void gemm_load_stage(
    uint32_t st,
    const __half* __restrict__ Ahi, const __half* __restrict__ Alo,
    const __half* __restrict__ B16,
    int bm, int bn, int k0, int K, int tid)
{
#pragma unroll
    for (int j = 0; j < 4; ++j) {
        int idx = tid + j * 128;            // 0..511
        int row = idx >> 2;                 // 0..127
        int c   = idx & 3;                  // 16B chunk within 64B row
        uint32_t off = GB_SWIZ(row, c);
        size_t ga = (size_t)(bm + row) * K + k0 + c * 8;
        size_t gb = (size_t)(bn + row) * K + k0 + c * 8;
        cp_async16(st + off,              Ahi + ga);
        cp_async16(st + GB_OP + off,      Alo + ga);
        cp_async16(st + 2 * GB_OP + off,  B16 + gb);
    }
}

__global__ __launch_bounds__(128, 2) void gemm_f16x2_kernel(
    const __half* __restrict__ Ahi, const __half* __restrict__ Alo,
    const __half* __restrict__ B16,
    const float* __restrict__ bias, float* __restrict__ C,
    int M, int N, int K, int fuse_qkv)
{
    extern __shared__ __align__(128) char smem[];
    const uint32_t sbase = smem_to_u32(smem);
    const int tid  = threadIdx.x;
    const int lane = tid & 31;
    const int wid  = tid >> 5;              // 0..3
    const int wm   = wid >> 1;              // 0..1 (64-row stripes)
    const int wn   = wid & 1;               // 0..1 (64-col stripes)
    const int bm   = blockIdx.y * 128;
    const int bn   = blockIdx.x * 128;

    float acc[4][8][4];
#pragma unroll
    for (int mi = 0; mi < 4; ++mi)
#pragma unroll
        for (int ni = 0; ni < 8; ++ni)
#pragma unroll
            for (int r = 0; r < 4; ++r) acc[mi][ni][r] = 0.f;

    const int nk = K / 32;

    gemm_load_stage(sbase,            Ahi, Alo, B16, bm, bn, 0,  K, tid);
    CP_ASYNC_COMMIT();
    gemm_load_stage(sbase + GB_STAGE, Ahi, Alo, B16, bm, bn, 32, K, tid);
    CP_ASYNC_COMMIT();

    const int lrowA = lane & 15, lcolA = lane >> 4;
    const int bg    = lane >> 3, blr  = lane & 7;

    for (int i = 0; i < nk; ++i) {
        const uint32_t st = sbase + (uint32_t)(i % GB_NSTAGE) * GB_STAGE;
        CP_ASYNC_WAIT_1();
        __syncthreads();

        if (i + 2 < nk) {
            gemm_load_stage(sbase + (uint32_t)((i + 2) % GB_NSTAGE) * GB_STAGE,
                            Ahi, Alo, B16, bm, bn, (i + 2) * 32, K, tid);
        }
        CP_ASYNC_COMMIT();

        const uint32_t aHi = st;
        const uint32_t aLo = st + GB_OP;
        const uint32_t bB  = st + 2 * GB_OP;

#pragma unroll
        for (int ks = 0; ks < 2; ++ks) {
            uint32_t ah[4][4], al[4][4];
#pragma unroll
            for (int mi = 0; mi < 4; ++mi) {
                int row = wm * 64 + mi * 16 + lrowA;
                uint32_t off = GB_SWIZ(row, ks * 2 + lcolA);
                ldsm4(ah[mi], aHi + off);
                ldsm4(al[mi], aLo + off);
            }
#pragma unroll
            for (int np = 0; np < 4; ++np) {
                uint32_t bh[4];
                int row = wn * 64 + np * 16 + (bg >> 1) * 8 + blr;
                uint32_t off = GB_SWIZ(row, ks * 2 + (bg & 1));
                ldsm4(bh, bB + off);
#pragma unroll
                for (int mi = 0; mi < 4; ++mi)
#pragma unroll
                    for (int q = 0; q < 2; ++q) {
                        int ni = np * 2 + q, pr = q * 2;
                        mma_f16(acc[mi][ni], ah[mi], bh[pr], bh[pr + 1]);
                        mma_f16(acc[mi][ni], al[mi], bh[pr], bh[pr + 1]);
                    }
            }
        }
    }

    const int gid = lane >> 2, tig = lane & 3;

    if (fuse_qkv == 0) {
#pragma unroll
        for (int mi = 0; mi < 4; ++mi)
#pragma unroll
            for (int ni = 0; ni < 8; ++ni) {
                int row = bm + wm * 64 + mi * 16 + gid;
                int col = bn + wn * 64 + ni * 8 + tig * 2;
                float2 bv = *(const float2*)(bias + col);
                float2 v0 = make_float2(acc[mi][ni][0] + bv.x, acc[mi][ni][1] + bv.y);
                float2 v1 = make_float2(acc[mi][ni][2] + bv.x, acc[mi][ni][3] + bv.y);
                *(float2*)(C + (size_t)row * N + col)       = v0;
                *(float2*)(C + (size_t)(row + 8) * N + col) = v1;
            }
        return;
    }

    // ---- fused QKV epilogue: rope/scale, fp16 head-major outputs ----
    __syncthreads();
    float* Cs = (float*)smem;                 // 128 x 132 fp32, reuses stages
#pragma unroll
    for (int mi = 0; mi < 4; ++mi)
#pragma unroll
        for (int ni = 0; ni < 8; ++ni) {
            int row = wm * 64 + mi * 16 + gid;
            int col = wn * 64 + ni * 8 + tig * 2;
            float2 bv = *(const float2*)(bias + bn + col);
            Cs[row * 132 + col]           = acc[mi][ni][0] + bv.x;
            Cs[row * 132 + col + 1]       = acc[mi][ni][1] + bv.y;
            Cs[(row + 8) * 132 + col]     = acc[mi][ni][2] + bv.x;
            Cs[(row + 8) * 132 + col + 1] = acc[mi][ni][3] + bv.y;
        }
    __syncthreads();

    const int sel = bn >> 11;                 // 0=Q, 1=K, 2=V
    const int hh  = (bn & 2047) >> 7;         // head
    const float SCALE = 0.08838834764831845f; // 1/sqrt(128)

    for (int i = tid; i < 128 * 32; i += 128) {
        int row = i >> 5, jp = (i & 31) * 2;
        int tg = bm + row, t = tg & (SEQ - 1), bb = tg >> 11;
        float x1a = Cs[row * 132 + jp],      x1b = Cs[row * 132 + jp + 1];
        float x2a = Cs[row * 132 + jp + 64], x2b = Cs[row * 132 + jp + 65];
        float y1a, y1b, y2a, y2b;
        if (sel < 2) {
            float cva = g_rope[t * 128 + jp],     sva = g_rope[t * 128 + 64 + jp];
            float cvb = g_rope[t * 128 + jp + 1], svb = g_rope[t * 128 + 64 + jp + 1];
            y1a = x1a * cva - x2a * sva;  y2a = x1a * sva + x2a * cva;
            y1b = x1b * cvb - x2b * svb;  y2b = x1b * svb + x2b * cvb;
            if (sel == 0) { y1a *= SCALE; y2a *= SCALE; y1b *= SCALE; y2b *= SCALE; }
        } else {
            y1a = x1a; y1b = x1b; y2a = x2a; y2b = x2b;
        }
        size_t base = ((size_t)(bb * N_HEAD + hh) * SEQ + t) * HEAD_DIM;
        if (sel == 1) {                       // K: plain fp16
            *(uint32_t*)(g_K16 + base + jp)      = pack2h(y1a, y1b);
            *(uint32_t*)(g_K16 + base + jp + 64) = pack2h(y2a, y2b);
        } else {                              // Q / V: fp16 hi/lo
            __half* dh = (sel == 0) ? g_Qhi : g_Vhi;
            __half* dl = (sel == 0) ? g_Qlo : g_Vlo;
            uint32_t hi, lo;
            split2h(y1a, y1b, hi, lo);
            *(uint32_t*)(dh + base + jp)      = hi;
            *(uint32_t*)(dl + base + jp)      = lo;
            split2h(y2a, y2b, hi, lo);
            *(uint32_t*)(dh + base + jp + 64) = hi;
            *(uint32_t*)(dl + base + jp + 64) = lo;
        }
    }
}

// ---------------------------------------------------------------------------
// fp16 MMA flash attention (R12 structure): Q hi/lo in regs, K plain,
// V hi/lo; tri-buffered KV + dedicated Q stage area; 1 sync/iter.
// S = qh*K + ql*K (2 MMA); O += p16 * (Vhi + Vlo) (2 MMA).
// ---------------------------------------------------------------------------
#define FA_TQ 128
#define FA_TK 64
#define FA_ROWB 272
#define FA_BUF  52224                 // K +0, VHI +17408, VLO +34816
#define FA_QAREA (3 * FA_BUF)         // Q staging: QHI +0, QLO +34816
#define FA_SMEM (3 * FA_BUF + 69632)  // 226304 B

__device__ __forceinline__ void fa_load_kv(uint32_t buf, size_t bh_elem, int k0, int tid)
{
    size_t gbase = bh_elem + (size_t)k0 * HEAD_DIM;
    for (int i = tid; i < FA_TK * 16; i += 256) {
        int row = i >> 4, c = i & 15;
        uint32_t soff = (uint32_t)(row * FA_ROWB + c * 16);
        size_t   goff = gbase + (size_t)row * HEAD_DIM + c * 8;
        cp_async16(buf + soff,         g_K16 + goff);
        cp_async16(buf + 17408 + soff, g_Vhi + goff);
        cp_async16(buf + 34816 + soff, g_Vlo + goff);
    }
}

__global__ __launch_bounds__(256, 1) void flash_attn_mma_kernel()
{
    extern __shared__ __align__(128) char sm[];
    const uint32_t sbase = smem_to_u32(sm);

    const int tid  = threadIdx.x;
    const int lane = tid & 31;
    const int wid  = tid >> 5;
    const int qt   = (gridDim.x - 1) - blockIdx.x;   // heavy tiles first
    const int q0   = qt * FA_TQ;
    const int b    = blockIdx.y >> 4;
    const int h    = blockIdx.y & 15;

    const size_t bh_elem = (size_t)(b * N_HEAD + h) * SEQ * HEAD_DIM;
    const int ktmax = 2 * qt + 1;                    // >= 1 always
    const uint32_t qarea = sbase + FA_QAREA;

    // ---- prologue loads: Q (g0), KV0 (g1), KV1 (g2) ----
    {
        size_t qbase = bh_elem + (size_t)q0 * HEAD_DIM;
        for (int i = tid; i < FA_TQ * 16; i += 256) {
            int row = i >> 4, c = i & 15;
            uint32_t soff = (uint32_t)(row * FA_ROWB + c * 16);
            size_t   goff = qbase + (size_t)row * HEAD_DIM + c * 8;
            cp_async16(qarea + soff,         g_Qhi + goff);
            cp_async16(qarea + 34816 + soff, g_Qlo + goff);
        }
    }
    CP_ASYNC_COMMIT();                               // g0: Q
    fa_load_kv(sbase, bh_elem, 0, tid);
    CP_ASYNC_COMMIT();                               // g1: KV0
    fa_load_kv(sbase + FA_BUF, bh_elem, FA_TK, tid);
    CP_ASYNC_COMMIT();                               // g2: KV1

    const int gid = lane >> 2, tig = lane & 3;
    const int lrowA = lane & 15, lcolA = lane >> 4;
    const int bg = lane >> 3, blr = lane & 7;
    const int wrow_lo = q0 + wid * 16;

    // ---- hoist Q into registers (dedicated area: never overwritten) ----
    uint32_t qh[8][4], ql[8][4];
    CP_ASYNC_WAIT_2();              // g0 (Q) complete
    __syncthreads();                // all threads' Q cp.asyncs visible
#pragma unroll
    for (int ks = 0; ks < 8; ++ks) {
        uint32_t qoff = (uint32_t)((wid * 16 + lrowA) * FA_ROWB
                                   + (ks * 16 + lcolA * 8) * 2);
        ldsm4(qh[ks], qarea + qoff);
        ldsm4(ql[ks], qarea + 34816 + qoff);
    }

    float oacc[16][4];
#pragma unroll
    for (int ni = 0; ni < 16; ++ni)
#pragma unroll
        for (int r = 0; r < 4; ++r) oacc[ni][r] = 0.f;
    float m0 = -1e30f, m1 = -1e30f, l0 = 0.f, l1 = 0.f;

    for (int kt = 0; kt <= ktmax; ++kt) {
        const int k0 = kt * FA_TK;
        const uint32_t buf = sbase + (uint32_t)(kt % 3) * FA_BUF;
        CP_ASYNC_WAIT_1();          // KV[kt] resident; KV[kt+1] may pend
        __syncthreads();            // data visible + prior-iter buffer reads done

        // prefetch KV[kt+2] into buf (kt+2)%3 (consumed at iter kt-1)
        if (kt + 2 <= ktmax)
            fa_load_kv(sbase + (uint32_t)((kt + 2) % 3) * FA_BUF,
                       bh_elem, (kt + 2) * FA_TK, tid);
        CP_ASYNC_COMMIT();

        if (k0 <= wrow_lo + 15) {   // warp-level causal skip
            // ---- S = (Qhi + Qlo) @ K^T, fp16 (2 MMAs/frag) ----
            float sacc[8][4];
#pragma unroll
            for (int ni = 0; ni < 8; ++ni)
#pragma unroll
                for (int r = 0; r < 4; ++r) sacc[ni][r] = 0.f;

#pragma unroll
            for (int ks = 0; ks < 8; ++ks) {
#pragma unroll
                for (int np = 0; np < 4; ++np) {
                    uint32_t kh[4];
                    uint32_t koff = (uint32_t)((np * 16 + (bg >> 1) * 8 + blr) * FA_ROWB
                                               + (ks * 16 + (bg & 1) * 8) * 2);
                    ldsm4(kh, buf + koff);
#pragma unroll
                    for (int q = 0; q < 2; ++q) {
                        int ni = np * 2 + q, pr = q * 2;
                        mma_f16(sacc[ni], qh[ks], kh[pr], kh[pr + 1]);
                        mma_f16(sacc[ni], ql[ks], kh[pr], kh[pr + 1]);
                    }
                }
            }

            // ---- causal mask (partial tiles only) ----
            const int row0 = wrow_lo + gid, row1 = row0 + 8;
            if (k0 + FA_TK - 1 > q0) {
#pragma unroll
                for (int ni = 0; ni < 8; ++ni) {
                    int col = k0 + ni * 8 + tig * 2;
                    if (col     > row0) sacc[ni][0] = -1e30f;
                    if (col + 1 > row0) sacc[ni][1] = -1e30f;
                    if (col     > row1) sacc[ni][2] = -1e30f;
                    if (col + 1 > row1) sacc[ni][3] = -1e30f;
                }
            }

            // ---- online softmax ----
            float mx0 = -1e30f, mx1 = -1e30f;
#pragma unroll
            for (int ni = 0; ni < 8; ++ni) {
                mx0 = fmaxf(mx0, fmaxf(sacc[ni][0], sacc[ni][1]));
                mx1 = fmaxf(mx1, fmaxf(sacc[ni][2], sacc[ni][3]));
            }
#pragma unroll
            for (int off = 1; off < 4; off <<= 1) {
                mx0 = fmaxf(mx0, __shfl_xor_sync(0xffffffffu, mx0, off));
                mx1 = fmaxf(mx1, __shfl_xor_sync(0xffffffffu, mx1, off));
            }
            float mn0 = fmaxf(m0, mx0), mn1 = fmaxf(m1, mx1);
            float a0 = __expf(m0 - mn0), a1 = __expf(m1 - mn1);
            m0 = mn0; m1 = mn1;
            float sum0 = 0.f, sum1 = 0.f;
#pragma unroll
            for (int ni = 0; ni < 8; ++ni) {
                sacc[ni][0] = __expf(sacc[ni][0] - mn0);
                sacc[ni][1] = __expf(sacc[ni][1] - mn0);
                sacc[ni][2] = __expf(sacc[ni][2] - mn1);
                sacc[ni][3] = __expf(sacc[ni][3] - mn1);
                sum0 += sacc[ni][0] + sacc[ni][1];
                sum1 += sacc[ni][2] + sacc[ni][3];
            }
#pragma unroll
            for (int off = 1; off < 4; off <<= 1) {
                sum0 += __shfl_xor_sync(0xffffffffu, sum0, off);
                sum1 += __shfl_xor_sync(0xffffffffu, sum1, off);
            }
            l0 = l0 * a0 + sum0;
            l1 = l1 * a1 + sum1;
#pragma unroll
            for (int ni = 0; ni < 16; ++ni) {
                oacc[ni][0] *= a0; oacc[ni][1] *= a0;
                oacc[ni][2] *= a1; oacc[ni][3] *= a1;
            }

            // ---- O += P16 @ (Vhi + Vlo), fp16 (2 MMAs/frag) ----
            const uint32_t vhi = buf + 17408, vlo = buf + 34816;
#pragma unroll
            for (int kc = 0; kc < 4; ++kc) {
                uint32_t ap[4];
                ap[0] = pack2h(sacc[2 * kc][0],     sacc[2 * kc][1]);
                ap[1] = pack2h(sacc[2 * kc][2],     sacc[2 * kc][3]);
                ap[2] = pack2h(sacc[2 * kc + 1][0], sacc[2 * kc + 1][1]);
                ap[3] = pack2h(sacc[2 * kc + 1][2], sacc[2 * kc + 1][3]);
#pragma unroll
                for (int np = 0; np < 8; ++np) {
                    uint32_t vh[4], vl[4];
                    uint32_t voff = (uint32_t)((kc * 16 + (lane & 15)) * FA_ROWB
                                               + (np * 16 + (lane >> 4) * 8) * 2);
                    ldsm4t(vh, vhi + voff);
                    ldsm4t(vl, vlo + voff);
#pragma unroll
                    for (int q = 0; q < 2; ++q) {
                        int ni = np * 2 + q, pr = q * 2;
                        mma_f16(oacc[ni], ap, vh[pr], vh[pr + 1]);
                        mma_f16(oacc[ni], ap, vl[pr], vl[pr + 1]);
                    }
                }
            }
        }
    }

    // ---- epilogue: normalize, split to fp16 hi/lo, store ----
    {
        float inv0 = 1.f / l0, inv1 = 1.f / l1;
        int t0 = wrow_lo + gid;
        size_t base0 = (size_t)(b * SEQ + t0) * D_MODEL + h * HEAD_DIM;
        size_t base1 = (size_t)(b * SEQ + t0 + 8) * D_MODEL + h * HEAD_DIM;
#pragma unroll
        for (int ni = 0; ni < 16; ++ni) {
            int col = ni * 8 + tig * 2;
            uint32_t hi, lo;
            split2h(oacc[ni][0] * inv0, oacc[ni][1] * inv0, hi, lo);
            *(uint32_t*)(g_Ahi + base0 + col) = hi;
            *(uint32_t*)(g_Alo + base0 + col) = lo;
            split2h(oacc[ni][2] * inv1, oacc[ni][3] * inv1, hi, lo);
            *(uint32_t*)(g_Ahi + base1 + col) = hi;
            *(uint32_t*)(g_Alo + base1 + col) = lo;
        }
    }
}

// ---------------------------------------------------------------------------
extern "C" void kernel_launch(void* const* d_in, const int* in_sizes, int n_in,
                              void* d_out, int out_size)
{
    (void)in_sizes; (void)n_in; (void)out_size;
    const float* x     = (const float*)d_in[0];
    const float* Wqkv  = (const float*)d_in[2];
    const float* bqkv  = (const float*)d_in[3];
    const float* Wproj = (const float*)d_in[4];
    const float* bproj = (const float*)d_in[5];
    float* out = (float*)d_out;

    void *xhi_p, *xlo_p, *wq16_p, *wp16_p, *ahi_p, *alo_p;
    cudaGetSymbolAddress(&xhi_p, g_Xhi);
    cudaGetSymbolAddress(&xlo_p, g_Xlo);
    cudaGetSymbolAddress(&wq16_p, g_Wqkv16);
    cudaGetSymbolAddress(&wp16_p, g_Wproj16);
    cudaGetSymbolAddress(&ahi_p, g_Ahi);
    cudaGetSymbolAddress(&alo_p, g_Alo);

    cudaFuncSetAttribute(gemm_f16x2_kernel,
                         cudaFuncAttributeMaxDynamicSharedMemorySize, GB_SMEM);
    cudaFuncSetAttribute(flash_attn_mma_kernel,
                         cudaFuncAttributeMaxDynamicSharedMemorySize, FA_SMEM);

    const int M = BATCH * SEQ;               // 4096
    const int nelem = M * D_MODEL;

    // 0) RoPE cos/sin table
    rope_table_kernel<<<SEQ * 64 / 256, 256>>>();

    // 1) split activations x -> fp16 (hi, lo)
    split_f16_kernel<<<(nelem / 4 + 255) / 256, 256>>>(x, nelem / 4);

    // 2) weight prep: both weights -> [N][K] plain fp16
    transpose_f16_kernel<<<dim3(3 * D_MODEL / 64, D_MODEL / 64), 256>>>(
        Wqkv, (__half*)wq16_p, D_MODEL, 3 * D_MODEL);
    transpose_f16_kernel<<<dim3(D_MODEL / 64, D_MODEL / 64), 256>>>(
        Wproj, (__half*)wp16_p, D_MODEL, D_MODEL);

    // 3) QKV projection, fp16x2, fused rope/split epilogue
    gemm_f16x2_kernel<<<dim3(3 * D_MODEL / 128, M / 128), 128, GB_SMEM>>>(
        (const __half*)xhi_p, (const __half*)xlo_p, (const __half*)wq16_p,
        bqkv, nullptr, M, 3 * D_MODEL, D_MODEL, 1);

    // 4) fp16 MMA flash attention (Q regs, tri-buffered KV)
    flash_attn_mma_kernel<<<dim3(SEQ / FA_TQ, BATCH * N_HEAD), 256, FA_SMEM>>>();

    // 5) output projection, fp16x2 (plain epilogue)
    gemm_f16x2_kernel<<<dim3(D_MODEL / 128, M / 128), 128, GB_SMEM>>>(
        (const __half*)ahi_p, (const __half*)alo_p, (const __half*)wp16_p,
        bproj, out, M, D_MODEL, D_MODEL, 0);
}

// round 17
// speedup vs baseline: 2.3627x; 1.6283x over previous
#include <cuda_runtime.h>
#include <cuda_fp16.h>
#include <math.h>
#include <stdint.h>

#define D_MODEL 2048
#define N_HEAD  16
#define HEAD_DIM 128
#define BATCH   2
#define SEQ     2048

// ---------------------------------------------------------------------------
// Static scratch (no cudaMalloc anywhere) — plain-fp16 pipeline, fp32 accum
// ---------------------------------------------------------------------------
static __device__ float g_rope[(size_t)SEQ * 128];                // cos/sin table
static __device__ __half g_X16[(size_t)BATCH * SEQ * D_MODEL];    // x fp16
static __device__ __half g_Wqkv16[(size_t)3 * D_MODEL * D_MODEL]; // [N][K] fp16
static __device__ __half g_Wproj16[(size_t)D_MODEL * D_MODEL];    // [N][K] fp16
static __device__ __half g_A16[(size_t)BATCH * SEQ * D_MODEL];    // attn out fp16
// head-major prepped attention operands: [b][h][t][d], all plain fp16
static __device__ __half g_Q16[(size_t)BATCH * SEQ * D_MODEL];
static __device__ __half g_K16[(size_t)BATCH * SEQ * D_MODEL];
static __device__ __half g_V16[(size_t)BATCH * SEQ * D_MODEL];

// ---------------------------------------------------------------------------
// PTX helpers (sm_80+ subset: cp.async / ldmatrix / mma.sync)
// ---------------------------------------------------------------------------
__device__ __forceinline__ uint32_t smem_to_u32(const void* smem_ptr) {
    uint32_t addr;
    asm("{ .reg .u64 tmp; cvta.to.shared.u64 tmp, %1; cvt.u32.u64 %0, tmp; }"
        : "=r"(addr) : "l"(smem_ptr));
    return addr;
}

__device__ __forceinline__ void cp_async16(uint32_t smem_dst, const void* gmem_src) {
    asm volatile("cp.async.cg.shared.global.L2::128B [%0], [%1], 16;"
                 :: "r"(smem_dst), "l"(__cvta_generic_to_global(gmem_src)));
}
#define CP_ASYNC_COMMIT() asm volatile("cp.async.commit_group;" ::: "memory")
#define CP_ASYNC_WAIT_1() asm volatile("cp.async.wait_group 1;" ::: "memory")
#define CP_ASYNC_WAIT_2() asm volatile("cp.async.wait_group 2;" ::: "memory")

__device__ __forceinline__ void ldsm4(uint32_t* r, uint32_t addr) {
    asm volatile("ldmatrix.sync.aligned.m8n8.x4.shared.b16 {%0,%1,%2,%3}, [%4];"
                 : "=r"(r[0]), "=r"(r[1]), "=r"(r[2]), "=r"(r[3]) : "r"(addr));
}
__device__ __forceinline__ void ldsm4t(uint32_t* r, uint32_t addr) {
    asm volatile("ldmatrix.sync.aligned.m8n8.x4.trans.shared.b16 {%0,%1,%2,%3}, [%4];"
                 : "=r"(r[0]), "=r"(r[1]), "=r"(r[2]), "=r"(r[3]) : "r"(addr));
}

__device__ __forceinline__ void mma_f16(float* c, const uint32_t* a,
                                        uint32_t b0, uint32_t b1) {
    asm volatile(
        "mma.sync.aligned.m16n8k16.row.col.f32.f16.f16.f32 "
        "{%0,%1,%2,%3}, {%4,%5,%6,%7}, {%8,%9}, {%0,%1,%2,%3};"
        : "+f"(c[0]), "+f"(c[1]), "+f"(c[2]), "+f"(c[3])
        : "r"(a[0]), "r"(a[1]), "r"(a[2]), "r"(a[3]), "r"(b0), "r"(b1));
}

__device__ __forceinline__ uint32_t pack2h(float s0, float s1) {
    uint32_t h;
    asm("cvt.rn.f16x2.f32 %0, %1, %2;" : "=r"(h) : "f"(s1), "f"(s0));
    return h;
}

// ---------------------------------------------------------------------------
// RoPE table
// ---------------------------------------------------------------------------
__global__ void rope_table_kernel()
{
    const float RATE_C = 0.14391156831212787f; // ln(10000)/64
    int i = blockIdx.x * blockDim.x + threadIdx.x;  // t*64 + j
    int t = i >> 6, j = i & 63;
    float rate = expf(-RATE_C * (float)j);
    float sv, cv;
    sincosf((float)t * rate, &sv, &cv);
    g_rope[t * 128 + j]      = cv;
    g_rope[t * 128 + 64 + j] = sv;
}

// ---------------------------------------------------------------------------
// x fp32 -> plain fp16
// ---------------------------------------------------------------------------
__global__ void convert_f16_kernel(const float* __restrict__ X, int n4)
{
    int i = blockIdx.x * blockDim.x + threadIdx.x;
    if (i >= n4) return;
    float4 v = *(const float4*)(X + (size_t)i * 4);
    *(uint2*)(g_X16 + (size_t)i * 4) =
        make_uint2(pack2h(v.x, v.y), pack2h(v.z, v.w));
}

// ---------------------------------------------------------------------------
// Transpose: W[K,N] fp32 -> dst[N,K] fp16 (plain).
// ---------------------------------------------------------------------------
__global__ __launch_bounds__(256) void transpose_f16_kernel(
    const float* __restrict__ W, __half* __restrict__ dst, int K, int N)
{
    __shared__ float tile[64][65];
    const int k0 = blockIdx.y * 64;
    const int n0 = blockIdx.x * 64;
    const int tid = threadIdx.x;

#pragma unroll
    for (int j = 0; j < 4; ++j) {
        int idx = tid + j * 256;
        int r  = idx >> 4;
        int c4 = (idx & 15) * 4;
        float4 v = *(const float4*)(W + (size_t)(k0 + r) * N + n0 + c4);
        tile[r][c4 + 0] = v.x; tile[r][c4 + 1] = v.y;
        tile[r][c4 + 2] = v.z; tile[r][c4 + 3] = v.w;
    }
    __syncthreads();

    const int n  = tid >> 2;
    const int ks = (tid & 3) * 16;
    __half h[16];
#pragma unroll
    for (int j = 0; j < 16; ++j)
        h[j] = __float2half_rn(tile[ks + j][n]);
    size_t base = (size_t)(n0 + n) * K + k0 + ks;
    *(uint4*)(dst + base)     = ((uint4*)h)[0];
    *(uint4*)(dst + base + 8) = ((uint4*)h)[1];
}

// ---------------------------------------------------------------------------
// fp16 HMMA GEMM: C = A16[M,K] @ B16[N,K]^T + bias (fp32 accum).
// 4 warps 2x2, 64x64 warp tiles, 3-stage XOR-swizzled cp.async (2 slots:
// A, B), 1 barrier/iter, 2 CTAs/SM. 1 MMA per fragment.
// fuse_qkv == 1: QKV epilogue (rope/scale -> plain fp16 Q/K/V head-major).
// ---------------------------------------------------------------------------
#define GB_OP     (128 * 64)                // 8192 B per operand tile
#define GB_STAGE  (2 * GB_OP)               // 16384 B
#define GB_NSTAGE 3
#define GB_SMEM   69632                     // >= max(3*16384, 128*132*4=67584)

#define GB_SWIZ(row, c) ((uint32_t)((row) * 64 + (((c) ^ (((row) >> 1) & 3)) * 16)))

__device__ __forceinline__ void gemm_load_stage(
    uint32_t st,
    const __half* __restrict__ A16, const __half* __restrict__ B16,
    int bm, int bn, int k0, int K, int tid)
{
#pragma unroll
    for (int j = 0; j < 4; ++j) {
        int idx = tid + j * 128;            // 0..511
        int row = idx >> 2;                 // 0..127
        int c   = idx & 3;                  // 16B chunk within 64B row
        uint32_t off = GB_SWIZ(row, c);
        cp_async16(st + off,         A16 + (size_t)(bm + row) * K + k0 + c * 8);
        cp_async16(st + GB_OP + off, B16 + (size_t)(bn + row) * K + k0 + c * 8);
    }
}

__global__ __launch_bounds__(128, 2) void gemm_f16_kernel(
    const __half* __restrict__ A16, const __half* __restrict__ B16,
    const float* __restrict__ bias, float* __restrict__ C,
    int M, int N, int K, int fuse_qkv)
{
    extern __shared__ __align__(128) char smem[];
    const uint32_t sbase = smem_to_u32(smem);
    const int tid  = threadIdx.x;
    const int lane = tid & 31;
    const int wid  = tid >> 5;              // 0..3
    const int wm   = wid >> 1;              // 0..1 (64-row stripes)
    const int wn   = wid & 1;               // 0..1 (64-col stripes)
    const int bm   = blockIdx.y * 128;
    const int bn   = blockIdx.x * 128;

    float acc[4][8][4];
#pragma unroll
    for (int mi = 0; mi < 4; ++mi)
#pragma unroll
        for (int ni = 0; ni < 8; ++ni)
#pragma unroll
            for (int r = 0; r < 4; ++r) acc[mi][ni][r] = 0.f;

    const int nk = K / 32;

    gemm_load_stage(sbase,            A16, B16, bm, bn, 0,  K, tid);
    CP_ASYNC_COMMIT();
    gemm_load_stage(sbase + GB_STAGE, A16, B16, bm, bn, 32, K, tid);
    CP_ASYNC_COMMIT();

    const int lrowA = lane & 15, lcolA = lane >> 4;
    const int bg    = lane >> 3, blr  = lane & 7;

    for (int i = 0; i < nk; ++i) {
        const uint32_t st = sbase + (uint32_t)(i % GB_NSTAGE) * GB_STAGE;
        CP_ASYNC_WAIT_1();
        __syncthreads();

        if (i + 2 < nk) {
            gemm_load_stage(sbase + (uint32_t)((i + 2) % GB_NSTAGE) * GB_STAGE,
                            A16, B16, bm, bn, (i + 2) * 32, K, tid);
        }
        CP_ASYNC_COMMIT();

        const uint32_t aA = st;
        const uint32_t bB = st + GB_OP;

#pragma unroll
        for (int ks = 0; ks < 2; ++ks) {
            uint32_t ah[4][4];
#pragma unroll
            for (int mi = 0; mi < 4; ++mi) {
                int row = wm * 64 + mi * 16 + lrowA;
                ldsm4(ah[mi], aA + GB_SWIZ(row, ks * 2 + lcolA));
            }
#pragma unroll
            for (int np = 0; np < 4; ++np) {
                uint32_t bh[4];
                int row = wn * 64 + np * 16 + (bg >> 1) * 8 + blr;
                ldsm4(bh, bB + GB_SWIZ(row, ks * 2 + (bg & 1)));
#pragma unroll
                for (int mi = 0; mi < 4; ++mi)
#pragma unroll
                    for (int q = 0; q < 2; ++q) {
                        int ni = np * 2 + q, pr = q * 2;
                        mma_f16(acc[mi][ni], ah[mi], bh[pr], bh[pr + 1]);
                    }
            }
        }
    }

    const int gid = lane >> 2, tig = lane & 3;

    if (fuse_qkv == 0) {
#pragma unroll
        for (int mi = 0; mi < 4; ++mi)
#pragma unroll
            for (int ni = 0; ni < 8; ++ni) {
                int row = bm + wm * 64 + mi * 16 + gid;
                int col = bn + wn * 64 + ni * 8 + tig * 2;
                float2 bv = *(const float2*)(bias + col);
                float2 v0 = make_float2(acc[mi][ni][0] + bv.x, acc[mi][ni][1] + bv.y);
                float2 v1 = make_float2(acc[mi][ni][2] + bv.x, acc[mi][ni][3] + bv.y);
                *(float2*)(C + (size_t)row * N + col)       = v0;
                *(float2*)(C + (size_t)(row + 8) * N + col) = v1;
            }
        return;
    }

    // ---- fused QKV epilogue: rope/scale -> plain fp16 head-major Q/K/V ----
    __syncthreads();
    float* Cs = (float*)smem;                 // 128 x 132 fp32, reuses stages
#pragma unroll
    for (int mi = 0; mi < 4; ++mi)
#pragma unroll
        for (int ni = 0; ni < 8; ++ni) {
            int row = wm * 64 + mi * 16 + gid;
            int col = wn * 64 + ni * 8 + tig * 2;
            float2 bv = *(const float2*)(bias + bn + col);
            Cs[row * 132 + col]           = acc[mi][ni][0] + bv.x;
            Cs[row * 132 + col + 1]       = acc[mi][ni][1] + bv.y;
            Cs[(row + 8) * 132 + col]     = acc[mi][ni][2] + bv.x;
            Cs[(row + 8) * 132 + col + 1] = acc[mi][ni][3] + bv.y;
        }
    __syncthreads();

    const int sel = bn >> 11;                 // 0=Q, 1=K, 2=V
    const int hh  = (bn & 2047) >> 7;         // head
    __half* dst = (sel == 0) ? g_Q16 : (sel == 1 ? g_K16 : g_V16);
    const float SCALE = 0.08838834764831845f; // 1/sqrt(128)

    for (int i = tid; i < 128 * 32; i += 128) {
        int row = i >> 5, jp = (i & 31) * 2;
        int tg = bm + row, t = tg & (SEQ - 1), bb = tg >> 11;
        float x1a = Cs[row * 132 + jp],      x1b = Cs[row * 132 + jp + 1];
        float x2a = Cs[row * 132 + jp + 64], x2b = Cs[row * 132 + jp + 65];
        float y1a, y1b, y2a, y2b;
        if (sel < 2) {
            float cva = g_rope[t * 128 + jp],     sva = g_rope[t * 128 + 64 + jp];
            float cvb = g_rope[t * 128 + jp + 1], svb = g_rope[t * 128 + 64 + jp + 1];
            y1a = x1a * cva - x2a * sva;  y2a = x1a * sva + x2a * cva;
            y1b = x1b * cvb - x2b * svb;  y2b = x1b * svb + x2b * cvb;
            if (sel == 0) { y1a *= SCALE; y2a *= SCALE; y1b *= SCALE; y2b *= SCALE; }
        } else {
            y1a = x1a; y1b = x1b; y2a = x2a; y2b = x2b;
        }
        size_t base = ((size_t)(bb * N_HEAD + hh) * SEQ + t) * HEAD_DIM;
        *(uint32_t*)(dst + base + jp)      = pack2h(y1a, y1b);
        *(uint32_t*)(dst + base + jp + 64) = pack2h(y2a, y2b);
    }
}

// ---------------------------------------------------------------------------
// fp16 MMA flash attention (R12 structure): Q in regs (staged via buf2 then
// recycled), tri-buffered plain-fp16 K/V, 1 sync/iter, prefetch before MMA.
// S = q*K (1 MMA/frag); O += p*V (1 MMA/frag). fp32 softmax/accum.
// ---------------------------------------------------------------------------
#define FA_TQ 128
#define FA_TK 64
#define FA_ROWB 272
#define FA_BUF  34816                 // K +0, V +17408
#define FA_SMEM (3 * FA_BUF)          // 104448; Q staged in buf2 then recycled

__device__ __forceinline__ void fa_load_kv(uint32_t buf, size_t bh_elem, int k0, int tid)
{
    size_t gbase = bh_elem + (size_t)k0 * HEAD_DIM;
    for (int i = tid; i < FA_TK * 16; i += 256) {
        int row = i >> 4, c = i & 15;
        uint32_t soff = (uint32_t)(row * FA_ROWB + c * 16);
        size_t   goff = gbase + (size_t)row * HEAD_DIM + c * 8;
        cp_async16(buf + soff,         g_K16 + goff);
        cp_async16(buf + 17408 + soff, g_V16 + goff);
    }
}

__global__ __launch_bounds__(256, 1) void flash_attn_mma_kernel()
{
    extern __shared__ __align__(128) char sm[];
    const uint32_t sbase = smem_to_u32(sm);

    const int tid  = threadIdx.x;
    const int lane = tid & 31;
    const int wid  = tid >> 5;
    const int qt   = (gridDim.x - 1) - blockIdx.x;   // heavy tiles first
    const int q0   = qt * FA_TQ;
    const int b    = blockIdx.y >> 4;
    const int h    = blockIdx.y & 15;

    const size_t bh_elem = (size_t)(b * N_HEAD + h) * SEQ * HEAD_DIM;
    const int ktmax = 2 * qt + 1;                    // >= 1 always

    // ---- prologue loads: Q -> buf2 region (g0), KV0 (g1), KV1 (g2) ----
    {
        size_t qbase = bh_elem + (size_t)q0 * HEAD_DIM;
        const uint32_t qarea = sbase + 2 * FA_BUF;   // 128 rows x 272 B
        for (int i = tid; i < FA_TQ * 16; i += 256) {
            int row = i >> 4, c = i & 15;
            uint32_t soff = (uint32_t)(row * FA_ROWB + c * 16);
            cp_async16(qarea + soff, g_Q16 + qbase + (size_t)row * HEAD_DIM + c * 8);
        }
    }
    CP_ASYNC_COMMIT();                               // g0: Q
    fa_load_kv(sbase, bh_elem, 0, tid);
    CP_ASYNC_COMMIT();                               // g1: KV0
    fa_load_kv(sbase + FA_BUF, bh_elem, FA_TK, tid);
    CP_ASYNC_COMMIT();                               // g2: KV1

    const int gid = lane >> 2, tig = lane & 3;
    const int lrowA = lane & 15, lcolA = lane >> 4;
    const int bg = lane >> 3, blr = lane & 7;
    const int wrow_lo = q0 + wid * 16;

    // ---- hoist Q into registers (then buf2 recycled as KV buffer) ----
    uint32_t qh[8][4];
    CP_ASYNC_WAIT_2();              // g0 (Q) complete
    __syncthreads();
    {
        const uint32_t qarea = sbase + 2 * FA_BUF;
#pragma unroll
        for (int ks = 0; ks < 8; ++ks) {
            uint32_t qoff = (uint32_t)((wid * 16 + lrowA) * FA_ROWB
                                       + (ks * 16 + lcolA * 8) * 2);
            ldsm4(qh[ks], qarea + qoff);
        }
    }
    __syncthreads();                // Q reads done -> buf2 free for KV2

    float oacc[16][4];
#pragma unroll
    for (int ni = 0; ni < 16; ++ni)
#pragma unroll
        for (int r = 0; r < 4; ++r) oacc[ni][r] = 0.f;
    float m0 = -1e30f, m1 = -1e30f, l0 = 0.f, l1 = 0.f;

    for (int kt = 0; kt <= ktmax; ++kt) {
        const int k0 = kt * FA_TK;
        const uint32_t buf = sbase + (uint32_t)(kt % 3) * FA_BUF;
        CP_ASYNC_WAIT_1();          // KV[kt] resident; KV[kt+1] may pend
        __syncthreads();            // data visible + prior-iter buffer reads done

        if (kt + 2 <= ktmax)        // prefetch overlaps MMA below
            fa_load_kv(sbase + (uint32_t)((kt + 2) % 3) * FA_BUF,
                       bh_elem, (kt + 2) * FA_TK, tid);
        CP_ASYNC_COMMIT();

        if (k0 <= wrow_lo + 15) {   // warp-level causal skip
            // ---- S = Q(regs) @ K^T, fp16 (1 MMA/frag) ----
            float sacc[8][4];
#pragma unroll
            for (int ni = 0; ni < 8; ++ni)
#pragma unroll
                for (int r = 0; r < 4; ++r) sacc[ni][r] = 0.f;

#pragma unroll
            for (int ks = 0; ks < 8; ++ks) {
#pragma unroll
                for (int np = 0; np < 4; ++np) {
                    uint32_t kh[4];
                    uint32_t koff = (uint32_t)((np * 16 + (bg >> 1) * 8 + blr) * FA_ROWB
                                               + (ks * 16 + (bg & 1) * 8) * 2);
                    ldsm4(kh, buf + koff);
#pragma unroll
                    for (int q = 0; q < 2; ++q) {
                        int ni = np * 2 + q, pr = q * 2;
                        mma_f16(sacc[ni], qh[ks], kh[pr], kh[pr + 1]);
                    }
                }
            }

            // ---- causal mask (partial tiles only) ----
            const int row0 = wrow_lo + gid, row1 = row0 + 8;
            if (k0 + FA_TK - 1 > q0) {
#pragma unroll
                for (int ni = 0; ni < 8; ++ni) {
                    int col = k0 + ni * 8 + tig * 2;
                    if (col     > row0) sacc[ni][0] = -1e30f;
                    if (col + 1 > row0) sacc[ni][1] = -1e30f;
                    if (col     > row1) sacc[ni][2] = -1e30f;
                    if (col + 1 > row1) sacc[ni][3] = -1e30f;
                }
            }

            // ---- online softmax (fp32) ----
            float mx0 = -1e30f, mx1 = -1e30f;
#pragma unroll
            for (int ni = 0; ni < 8; ++ni) {
                mx0 = fmaxf(mx0, fmaxf(sacc[ni][0], sacc[ni][1]));
                mx1 = fmaxf(mx1, fmaxf(sacc[ni][2], sacc[ni][3]));
            }
#pragma unroll
            for (int off = 1; off < 4; off <<= 1) {
                mx0 = fmaxf(mx0, __shfl_xor_sync(0xffffffffu, mx0, off));
                mx1 = fmaxf(mx1, __shfl_xor_sync(0xffffffffu, mx1, off));
            }
            float mn0 = fmaxf(m0, mx0), mn1 = fmaxf(m1, mx1);
            float a0 = __expf(m0 - mn0), a1 = __expf(m1 - mn1);
            m0 = mn0; m1 = mn1;
            float sum0 = 0.f, sum1 = 0.f;
#pragma unroll
            for (int ni = 0; ni < 8; ++ni) {
                sacc[ni][0] = __expf(sacc[ni][0] - mn0);
                sacc[ni][1] = __expf(sacc[ni][1] - mn0);
                sacc[ni][2] = __expf(sacc[ni][2] - mn1);
                sacc[ni][3] = __expf(sacc[ni][3] - mn1);
                sum0 += sacc[ni][0] + sacc[ni][1];
                sum1 += sacc[ni][2] + sacc[ni][3];
            }
#pragma unroll
            for (int off = 1; off < 4; off <<= 1) {
                sum0 += __shfl_xor_sync(0xffffffffu, sum0, off);
                sum1 += __shfl_xor_sync(0xffffffffu, sum1, off);
            }
            l0 = l0 * a0 + sum0;
            l1 = l1 * a1 + sum1;
#pragma unroll
            for (int ni = 0; ni < 16; ++ni) {
                oacc[ni][0] *= a0; oacc[ni][1] *= a0;
                oacc[ni][2] *= a1; oacc[ni][3] *= a1;
            }

            // ---- O += P16 @ V, fp16 (1 MMA/frag) ----
            const uint32_t vv = buf + 17408;
#pragma unroll
            for (int kc = 0; kc < 4; ++kc) {
                uint32_t ap[4];
                ap[0] = pack2h(sacc[2 * kc][0],     sacc[2 * kc][1]);
                ap[1] = pack2h(sacc[2 * kc][2],     sacc[2 * kc][3]);
                ap[2] = pack2h(sacc[2 * kc + 1][0], sacc[2 * kc + 1][1]);
                ap[3] = pack2h(sacc[2 * kc + 1][2], sacc[2 * kc + 1][3]);
#pragma unroll
                for (int np = 0; np < 8; ++np) {
                    uint32_t vh[4];
                    uint32_t voff = (uint32_t)((kc * 16 + (lane & 15)) * FA_ROWB
                                               + (np * 16 + (lane >> 4) * 8) * 2);
                    ldsm4t(vh, vv + voff);
#pragma unroll
                    for (int q = 0; q < 2; ++q) {
                        int ni = np * 2 + q, pr = q * 2;
                        mma_f16(oacc[ni], ap, vh[pr], vh[pr + 1]);
                    }
                }
            }
        }
    }

    // ---- epilogue: normalize, store plain fp16 ----
    {
        float inv0 = 1.f / l0, inv1 = 1.f / l1;
        int t0 = wrow_lo + gid;
        size_t base0 = (size_t)(b * SEQ + t0) * D_MODEL + h * HEAD_DIM;
        size_t base1 = (size_t)(b * SEQ + t0 + 8) * D_MODEL + h * HEAD_DIM;
#pragma unroll
        for (int ni = 0; ni < 16; ++ni) {
            int col = ni * 8 + tig * 2;
            *(uint32_t*)(g_A16 + base0 + col) =
                pack2h(oacc[ni][0] * inv0, oacc[ni][1] * inv0);
            *(uint32_t*)(g_A16 + base1 + col) =
                pack2h(oacc[ni][2] * inv1, oacc[ni][3] * inv1);
        }
    }
}

// ---------------------------------------------------------------------------
extern "C" void kernel_launch(void* const* d_in, const int* in_sizes, int n_in,
                              void* d_out, int out_size)
{
    (void)in_sizes; (void)n_in; (void)out_size;
    const float* x     = (const float*)d_in[0];
    const float* Wqkv  = (const float*)d_in[2];
    const float* bqkv  = (const float*)d_in[3];
    const float* Wproj = (const float*)d_in[4];
    const float* bproj = (const float*)d_in[5];
    float* out = (float*)d_out;

    void *x16_p, *wq16_p, *wp16_p, *a16_p;
    cudaGetSymbolAddress(&x16_p, g_X16);
    cudaGetSymbolAddress(&wq16_p, g_Wqkv16);
    cudaGetSymbolAddress(&wp16_p, g_Wproj16);
    cudaGetSymbolAddress(&a16_p, g_A16);

    cudaFuncSetAttribute(gemm_f16_kernel,
                         cudaFuncAttributeMaxDynamicSharedMemorySize, GB_SMEM);
    cudaFuncSetAttribute(flash_attn_mma_kernel,
                         cudaFuncAttributeMaxDynamicSharedMemorySize, FA_SMEM);

    const int M = BATCH * SEQ;               // 4096
    const int nelem = M * D_MODEL;

    // 0) RoPE cos/sin table
    rope_table_kernel<<<SEQ * 64 / 256, 256>>>();

    // 1) x -> plain fp16
    convert_f16_kernel<<<(nelem / 4 + 255) / 256, 256>>>(x, nelem / 4);

    // 2) weight prep: both weights -> [N][K] plain fp16
    transpose_f16_kernel<<<dim3(3 * D_MODEL / 64, D_MODEL / 64), 256>>>(
        Wqkv, (__half*)wq16_p, D_MODEL, 3 * D_MODEL);
    transpose_f16_kernel<<<dim3(D_MODEL / 64, D_MODEL / 64), 256>>>(
        Wproj, (__half*)wp16_p, D_MODEL, D_MODEL);

    // 3) QKV projection, plain fp16, fused rope epilogue
    gemm_f16_kernel<<<dim3(3 * D_MODEL / 128, M / 128), 128, GB_SMEM>>>(
        (const __half*)x16_p, (const __half*)wq16_p,
        bqkv, nullptr, M, 3 * D_MODEL, D_MODEL, 1);

    // 4) fp16 MMA flash attention
    flash_attn_mma_kernel<<<dim3(SEQ / FA_TQ, BATCH * N_HEAD), 256, FA_SMEM>>>();

    // 5) output projection, plain fp16
    gemm_f16_kernel<<<dim3(D_MODEL / 128, M / 128), 128, GB_SMEM>>>(
        (const __half*)a16_p, (const __half*)wp16_p,
        bproj, out, M, D_MODEL, D_MODEL, 0);
}